// round 12
// baseline (speedup 1.0000x reference)
#include <cuda_runtime.h>
#include <cuda_bf16.h>
#include <math.h>
#include <stdint.h>

#define N_NODES   65536
#define NUM_G     512
#define MAX_N     192
#define DIM       512
#define HEADS     8
#define DH        64
#define QMAX      16
#define KS2       33
#define SSTR      192
#define XPARTS    4

// ---- K projection GEMM config: CTA 128x128, 4 warps of 64x64 ----
#define BM 128
#define BN 128
#define NCHUNK 24
#define GEMM_SMEM (6 * 16384)

// ---------------- device scratch ----------------
__device__ float         g_K[(size_t)N_NODES * 512];
__device__ __nv_bfloat16 g_Xx[(size_t)N_NODES * 1024];
__device__ __nv_bfloat16 g_Wx[(size_t)512 * 1024];
__device__ float         g_bK[512];
__device__ float         g_Wqb[HEADS * 8 * 8 * 64];
__device__ float         g_avgw[NUM_G * HEADS * MAX_N];
__device__ float         g_xbar[XPARTS * NUM_G * HEADS * DIM];
__device__ float         g_pooled[NUM_G * DIM];
__device__ float         g_tmp[NUM_G * DIM];
__device__ int           g_counts[NUM_G];
__device__ int           g_offsets[NUM_G];

// ---------------- helpers ----------------
__device__ __forceinline__ uint32_t smem_u32(const void* p) {
    uint32_t a;
    asm("{ .reg .u64 t; cvta.to.shared.u64 t, %1; cvt.u32.u64 %0, t; }" : "=r"(a) : "l"(p));
    return a;
}
#define SWZ(b) ((b) ^ (((b) >> 3) & 0x70))

__device__ __forceinline__ void cp_async16(uint32_t dst, const void* src) {
    asm volatile("cp.async.cg.shared.global [%0], [%1], 16;" :: "r"(dst), "l"(src));
}
__device__ __forceinline__ void cp_commit() {
    asm volatile("cp.async.commit_group;" ::: "memory");
}
template <int N> __device__ __forceinline__ void cp_wait() {
    asm volatile("cp.async.wait_group %0;" :: "n"(N) : "memory");
}
__device__ __forceinline__ void ldm_x4(uint32_t& r0, uint32_t& r1, uint32_t& r2, uint32_t& r3,
                                       uint32_t addr) {
    asm volatile("ldmatrix.sync.aligned.m8n8.x4.shared.b16 {%0,%1,%2,%3}, [%4];"
                 : "=r"(r0), "=r"(r1), "=r"(r2), "=r"(r3) : "r"(addr));
}
__device__ __forceinline__ void mma_bf16(float& d0, float& d1, float& d2, float& d3,
                                         uint32_t a0, uint32_t a1, uint32_t a2, uint32_t a3,
                                         uint32_t b0, uint32_t b1) {
    asm volatile("mma.sync.aligned.m16n8k16.row.col.f32.bf16.bf16.f32 "
                 "{%0,%1,%2,%3}, {%4,%5,%6,%7}, {%8,%9}, {%0,%1,%2,%3};"
                 : "+f"(d0), "+f"(d1), "+f"(d2), "+f"(d3)
                 : "r"(a0), "r"(a1), "r"(a2), "r"(a3), "r"(b0), "r"(b1));
}

__device__ __forceinline__ void split4(float4 v, uint2* hi, uint2* lo) {
    __nv_bfloat16 h0 = __float2bfloat16_rn(v.x), h1 = __float2bfloat16_rn(v.y);
    __nv_bfloat16 h2 = __float2bfloat16_rn(v.z), h3 = __float2bfloat16_rn(v.w);
    __nv_bfloat16 l0 = __float2bfloat16_rn(v.x - __bfloat162float(h0));
    __nv_bfloat16 l1 = __float2bfloat16_rn(v.y - __bfloat162float(h1));
    __nv_bfloat16 l2 = __float2bfloat16_rn(v.z - __bfloat162float(h2));
    __nv_bfloat16 l3 = __float2bfloat16_rn(v.w - __bfloat162float(h3));
    hi->x = (uint32_t)__bfloat16_as_ushort(h0) | ((uint32_t)__bfloat16_as_ushort(h1) << 16);
    hi->y = (uint32_t)__bfloat16_as_ushort(h2) | ((uint32_t)__bfloat16_as_ushort(h3) << 16);
    lo->x = (uint32_t)__bfloat16_as_ushort(l0) | ((uint32_t)__bfloat16_as_ushort(l1) << 16);
    lo->y = (uint32_t)__bfloat16_as_ushort(l2) | ((uint32_t)__bfloat16_as_ushort(l3) << 16);
}

// ---------------- wqb precompute ----------------
__global__ void __launch_bounds__(512) wqb_kernel(const float* __restrict__ gq,
                                                  const float* __restrict__ wq) {
    __shared__ float gqs[512];
    __shared__ float wsh[64 * 65];
    int h = blockIdx.x >> 3, j = blockIdx.x & 7;
    int tid = threadIdx.x;
    gqs[tid] = gq[tid];
    for (int idx = tid; idx < 64 * 64; idx += 512) {
        int row = idx >> 6, cc = idx & 63;
        wsh[row * 65 + cc] = wq[(size_t)(h * 64 + row) * 512 + j * 64 + cc];
    }
    __syncthreads();
    int ol = tid & 63, hh = tid >> 6;
    float v = 0.f;
#pragma unroll 8
    for (int r = 0; r < 64; r++) v += gqs[hh * 64 + r] * wsh[ol * 65 + r];
    g_Wqb[h * 4096 + (j * 8 + hh) * 64 + ol] = v;
}

// ---------------- counts + bias ----------------
__global__ void __launch_bounds__(512) counts_kernel(const int* __restrict__ bidx,
                                                     const float* __restrict__ bk) {
    __shared__ int lb[NUM_G + 1];
    int g = threadIdx.x;
    int lo = 0, hi = N_NODES;
    while (lo < hi) { int mid = (lo + hi) >> 1; if (bidx[mid] < g) lo = mid + 1; else hi = mid; }
    lb[g] = lo;
    if (g == 0) lb[NUM_G] = N_NODES;
    __syncthreads();
    g_offsets[g] = lb[g];
    g_counts[g]  = lb[g + 1] - lb[g];
    g_bK[g] = bk[g];
}

// ---------------- convw ----------------
__global__ void __launch_bounds__(512) convw_kernel(const float* __restrict__ wk) {
    int i = blockIdx.x * 512 + threadIdx.x;
    int r = i >> 7;
    int c4 = i & 127;
    float4 v = ((const float4*)wk)[(size_t)r * 128 + c4];
    uint2 hi, lo;
    split4(v, &hi, &lo);
    ((uint2*)(g_Wx + (size_t)r * 1024))[c4]       = hi;
    ((uint2*)(g_Wx + (size_t)r * 1024 + 512))[c4] = lo;
}

// ---------------- convx (4th launch = profiled slot) ----------------
__global__ void __launch_bounds__(256) convx_kernel(const float* __restrict__ x) {
    size_t i = (size_t)blockIdx.x * 256 + threadIdx.x;
    float4 v = ((const float4*)x)[i];
    size_t r = i >> 7;
    int c4 = (int)(i & 127);
    uint2 hi, lo;
    split4(v, &hi, &lo);
    ((uint2*)(g_Xx + r * 1024))[c4]       = hi;
    ((uint2*)(g_Xx + r * 1024 + 512))[c4] = lo;
}

// ---------------- bf16 mma.sync K GEMM: 4 warps of 64x64 ----------------
__device__ __forceinline__ int a_index(int c) { return (c < 16) ? (c >> 1) : (c - 8); }

__device__ __forceinline__ void gemm_load_chunk(uint32_t sbase, int m0, int n0, int c, int tid) {
    int kq, kx, kw;
    bool loadA;
    if (c < 16) { kq = c >> 1; kx = kq * 64;       kw = kq * 64 + ((c & 1) ? 512 : 0); loadA = !(c & 1); }
    else        { kq = c - 16; kx = kq * 64 + 512; kw = kq * 64;                        loadA = true; }
    uint32_t sA = sbase + (uint32_t)(a_index(c) % 3) * 16384u;
    uint32_t sB = sbase + 49152u + (uint32_t)(c % 3) * 16384u;
    if (loadA) {
#pragma unroll
        for (int u = 0; u < 8; u++) {
            int idx = tid + u * 128;
            int row = idx >> 3;
            int cb = (idx & 7) * 16;
            cp_async16(sA + SWZ(row * 128 + cb),
                       (const char*)(g_Xx + (size_t)(m0 + row) * 1024 + kx) + cb);
        }
    }
#pragma unroll
    for (int u = 0; u < 8; u++) {
        int idx = tid + u * 128;
        int row = idx >> 3;
        int cb = (idx & 7) * 16;
        cp_async16(sB + SWZ(row * 128 + cb),
                   (const char*)(g_Wx + (size_t)(n0 + row) * 1024 + kw) + cb);
    }
    cp_commit();
}

__global__ void __launch_bounds__(128, 2) kv_gemm_kernel() {
    extern __shared__ char smem[];
    uint32_t sbase = smem_u32(smem);
    int tid = threadIdx.x;
    int lane = tid & 31, w = tid >> 5;
    int wm = w >> 1, wn = w & 1;
    int m0 = blockIdx.y * BM;
    int n0 = blockIdx.x * BN;

    float acc[4][8][4];
#pragma unroll
    for (int i = 0; i < 4; i++)
#pragma unroll
        for (int j = 0; j < 8; j++)
#pragma unroll
            for (int k = 0; k < 4; k++) acc[i][j][k] = 0.f;

    gemm_load_chunk(sbase, m0, n0, 0, tid);
    gemm_load_chunk(sbase, m0, n0, 1, tid);

    int lrow = ((lane >> 3) & 1) * 8 + (lane & 7);
    int lcol = ((lane >> 4) & 1) * 16;

    for (int c = 0; c < NCHUNK; c++) {
        if (c < NCHUNK - 1) cp_wait<1>(); else cp_wait<0>();
        __syncthreads();
        if (c + 2 < NCHUNK) gemm_load_chunk(sbase, m0, n0, c + 2, tid);

        uint32_t sA = sbase + (uint32_t)(a_index(c) % 3) * 16384u;
        uint32_t sB = sbase + 49152u + (uint32_t)(c % 3) * 16384u;

#pragma unroll
        for (int ks = 0; ks < 4; ks++) {
            uint32_t a[4][4], b[4][4];
#pragma unroll
            for (int mt = 0; mt < 4; mt++) {
                uint32_t addr = sA + SWZ((wm * 64 + mt * 16 + lrow) * 128 + ks * 32 + lcol);
                ldm_x4(a[mt][0], a[mt][1], a[mt][2], a[mt][3], addr);
            }
#pragma unroll
            for (int nt = 0; nt < 4; nt++) {
                uint32_t addr = sB + SWZ((wn * 64 + nt * 16 + lrow) * 128 + ks * 32 + lcol);
                ldm_x4(b[nt][0], b[nt][1], b[nt][2], b[nt][3], addr);
            }
#pragma unroll
            for (int mt = 0; mt < 4; mt++)
#pragma unroll
                for (int nt = 0; nt < 8; nt++) {
                    uint32_t b0 = b[nt >> 1][(nt & 1) ? 1 : 0];
                    uint32_t b1 = b[nt >> 1][(nt & 1) ? 3 : 2];
                    mma_bf16(acc[mt][nt][0], acc[mt][nt][1], acc[mt][nt][2], acc[mt][nt][3],
                             a[mt][0], a[mt][1], a[mt][2], a[mt][3], b0, b1);
                }
        }
    }

    int mrow = lane >> 2;
    int ncol = (lane & 3) * 2;
#pragma unroll
    for (int mt = 0; mt < 4; mt++) {
#pragma unroll
        for (int nt = 0; nt < 8; nt++) {
            int m = m0 + wm * 64 + mt * 16 + mrow;
            int n = n0 + wn * 64 + nt * 8 + ncol;
            float2 bias = *(const float2*)&g_bK[n];
            float2 v0 = make_float2(acc[mt][nt][0] + bias.x, acc[mt][nt][1] + bias.y);
            float2 v1 = make_float2(acc[mt][nt][2] + bias.x, acc[mt][nt][3] + bias.y);
            *(float2*)&g_K[(size_t)m * 512 + n] = v0;
            *(float2*)&g_K[(size_t)(m + 8) * 512 + n] = v1;
        }
    }
}

// ---------------- small SGEMM 32x32 tiles ----------------
template <bool RELU>
__global__ void __launch_bounds__(128) sgemm32_kernel(
    const float* __restrict__ A, const float* __restrict__ B,
    const float* __restrict__ bias, float* __restrict__ C,
    int M, int N, int K)
{
    __shared__ float As[16][32];
    __shared__ float Bs[16][32];
    int tid = threadIdx.x;
    int m0 = blockIdx.y * 32;
    int n0 = blockIdx.x * 32;
    int tr = tid >> 3, tc = tid & 7;
    int lr = tid >> 2;
    int lc = (tid & 3) * 4;
    float acc[2][4];
#pragma unroll
    for (int i = 0; i < 2; i++)
#pragma unroll
        for (int j = 0; j < 4; j++) acc[i][j] = 0.f;

    for (int k0 = 0; k0 < K; k0 += 16) {
        float4 a = *(const float4*)(A + (size_t)(m0 + lr) * K + k0 + lc);
        As[lc + 0][lr] = a.x; As[lc + 1][lr] = a.y; As[lc + 2][lr] = a.z; As[lc + 3][lr] = a.w;
        float4 b = *(const float4*)(B + (size_t)(n0 + lr) * K + k0 + lc);
        Bs[lc + 0][lr] = b.x; Bs[lc + 1][lr] = b.y; Bs[lc + 2][lr] = b.z; Bs[lc + 3][lr] = b.w;
        __syncthreads();
#pragma unroll
        for (int kk = 0; kk < 16; kk++) {
            float am[2], bn[4];
#pragma unroll
            for (int i = 0; i < 2; i++) am[i] = As[kk][tr * 2 + i];
#pragma unroll
            for (int j = 0; j < 4; j++) bn[j] = Bs[kk][tc * 4 + j];
#pragma unroll
            for (int i = 0; i < 2; i++)
#pragma unroll
                for (int j = 0; j < 4; j++) acc[i][j] = fmaf(am[i], bn[j], acc[i][j]);
        }
        __syncthreads();
    }
#pragma unroll
    for (int i = 0; i < 2; i++) {
        int m = m0 + tr * 2 + i;
#pragma unroll
        for (int j = 0; j < 4; j++) {
            int n = n0 + tc * 4 + j;
            float v = acc[i][j] + bias[n];
            if (RELU) v = fmaxf(v, 0.f);
            C[(size_t)m * N + n] = v;
        }
    }
}

// ---------------- V projection on xbar (sums XPARTS partials) ----------------
__global__ void __launch_bounds__(128) vproj_kernel(const float* __restrict__ wv,
                                                    const float* __restrict__ bv)
{
    __shared__ float As[16][64];
    __shared__ float Bs[16][64];
    int tid = threadIdx.x;
    int h = blockIdx.y;
    int m0 = blockIdx.x * 64;
    int tr = tid >> 3, tc = tid & 7;
    int lr = tid >> 2;
    int lc = (tid & 3) * 4;
    float acc[4][8];
#pragma unroll
    for (int i = 0; i < 4; i++)
#pragma unroll
        for (int j = 0; j < 8; j++) acc[i][j] = 0.f;

    const size_t PSTRIDE = (size_t)NUM_G * HEADS * DIM;

    for (int k0 = 0; k0 < 512; k0 += 16) {
#pragma unroll
        for (int p = 0; p < 2; p++) {
            int r = lr + 32 * p;
            size_t base = ((size_t)(m0 + r) * 8 + h) * 512 + k0 + lc;
            float4 a = *(const float4*)(g_xbar + base);
#pragma unroll
            for (int q = 1; q < XPARTS; q++) {
                float4 a2 = *(const float4*)(g_xbar + q * PSTRIDE + base);
                a.x += a2.x; a.y += a2.y; a.z += a2.z; a.w += a2.w;
            }
            As[lc + 0][r] = a.x; As[lc + 1][r] = a.y; As[lc + 2][r] = a.z; As[lc + 3][r] = a.w;
            float4 b = *(const float4*)(wv + (size_t)(h * 64 + r) * 512 + k0 + lc);
            Bs[lc + 0][r] = b.x; Bs[lc + 1][r] = b.y; Bs[lc + 2][r] = b.z; Bs[lc + 3][r] = b.w;
        }
        __syncthreads();
#pragma unroll
        for (int kk = 0; kk < 16; kk++) {
            float am[4], bn[8];
#pragma unroll
            for (int i = 0; i < 4; i++) am[i] = As[kk][tr * 4 + i];
#pragma unroll
            for (int j = 0; j < 8; j++) bn[j] = Bs[kk][tc * 8 + j];
#pragma unroll
            for (int i = 0; i < 4; i++)
#pragma unroll
                for (int j = 0; j < 8; j++) acc[i][j] = fmaf(am[i], bn[j], acc[i][j]);
        }
        __syncthreads();
    }
#pragma unroll
    for (int i = 0; i < 4; i++) {
        int m = m0 + tr * 4 + i;
        int cnt = g_counts[m];
        int nn = cnt < MAX_N ? cnt : MAX_N;
        float scale = (cnt > 0) ? (float)nn / (float)cnt : 0.f;
#pragma unroll
        for (int j = 0; j < 8; j++) {
            int nc = tc * 8 + j;
            g_pooled[(size_t)m * DIM + h * 64 + nc] = acc[i][j] + scale * bv[h * 64 + nc];
        }
    }
}

// ---------------- xbar: s-split partial weighted x sums ----------------
__global__ void __launch_bounds__(256) xbar_kernel(const float* __restrict__ x) {
    int g = blockIdx.x;
    int part = blockIdx.y;
    int ntrue = g_counts[g];
    int off = g_offsets[g];
    int n = ntrue < MAX_N ? ntrue : MAX_N;
    __shared__ float aw[HEADS * MAX_N];
    int tid = threadIdx.x;

    float acc[HEADS][2];
#pragma unroll
    for (int h = 0; h < HEADS; h++) { acc[h][0] = 0.f; acc[h][1] = 0.f; }

    if (n > 0) {
#pragma unroll
        for (int h = 0; h < HEADS; h++)
            for (int s = tid; s < n; s += 256)
                aw[h * MAX_N + s] = g_avgw[((size_t)g * HEADS + h) * MAX_N + s];
        __syncthreads();

        const float* xb = x + (size_t)off * 512;
        for (int s = part; s < n; s += XPARTS) {
            float x0 = xb[(size_t)s * 512 + tid];
            float x1 = xb[(size_t)s * 512 + tid + 256];
#pragma unroll
            for (int h = 0; h < HEADS; h++) {
                float wv = aw[h * MAX_N + s];
                acc[h][0] = fmaf(wv, x0, acc[h][0]);
                acc[h][1] = fmaf(wv, x1, acc[h][1]);
            }
        }
    }
    size_t pbase = (size_t)part * NUM_G * HEADS * DIM;
#pragma unroll
    for (int h = 0; h < HEADS; h++) {
        g_xbar[pbase + ((size_t)g * HEADS + h) * 512 + tid]       = acc[h][0];
        g_xbar[pbase + ((size_t)g * HEADS + h) * 512 + tid + 256] = acc[h][1];
    }
}

// ---------------- attention: task-parallel scores + smem staging ----------------
__device__ __forceinline__ float warp_max(float v) {
#pragma unroll
    for (int o = 16; o > 0; o >>= 1) v = fmaxf(v, __shfl_xor_sync(0xffffffffu, v, o));
    return v;
}
__device__ __forceinline__ float warp_sum(float v) {
#pragma unroll
    for (int o = 16; o > 0; o >>= 1) v += __shfl_xor_sync(0xffffffffu, v, o);
    return v;
}

// smem floats: Ksh 6336 + scores 3072 + Qcls 1024 + mu 16 + su 16 + hpack 192 + uhp 16 + ucnt 16 + wcnt 12
#define ATT_SMEM ((6336 + 3072 + 1024 + 16 + 16 + 192 + 16 + 16 + 12) * 4)

__global__ void __launch_bounds__(256) attn_kernel(const float* __restrict__ bq)
{
    int g = blockIdx.x, h = blockIdx.y;
    int ntrue = g_counts[g];
    int off = g_offsets[g];
    extern __shared__ float sm[];
    float*    Ksh    = sm;                          // 192*33
    float*    scores = Ksh + MAX_N * KS2;           // 16*192
    float*    Qcls   = scores + QMAX * SSTR;        // 16*64
    float*    smu    = Qcls + QMAX * 64;            // 16 (class max)
    float*    ssc    = smu + QMAX;                  // 16 (class scale)
    unsigned* hpack  = (unsigned*)(ssc + QMAX);     // 192
    unsigned* uhp    = hpack + MAX_N;               // 16
    float*    ucnt   = (float*)(uhp + QMAX);        // 16
    int*      wcnt   = (int*)(ucnt + QMAX);         // 12

    int tid = threadIdx.x, lane = tid & 31, w = tid >> 5;

    if (ntrue <= 0) return;
    int n = ntrue < MAX_N ? ntrue : MAX_N;

    // K columns [0,32)
    for (int idx = tid; idx < n * 32; idx += 256) {
        int s = idx >> 5, c = idx & 31;
        Ksh[s * KS2 + c] = g_K[(size_t)(off + s) * 512 + h * 64 + c];
    }
    if (tid < QMAX) { ucnt[tid] = 0.f; uhp[tid] = 0u; }
    for (int t = tid; t < n; t += 256) {
        unsigned p = 0;
#pragma unroll
        for (int j = 0; j < 8; j++) {
            unsigned hh = (unsigned)(8 * t + j) / (unsigned)ntrue;
            if (hh > 7) hh = 7;
            p |= hh << (3 * j);
        }
        hpack[t] = p;
    }
    __syncthreads();

    // run-length classify (U <= 15)
    int t = tid;
    int isb = (t < n) && (t == 0 || hpack[t] != hpack[t - 1]);
    unsigned bits = __ballot_sync(0xffffffffu, isb);
    if (lane == 31) wcnt[w] = __popc(bits);
    __syncthreads();
    if (tid == 0) {
        int s = 0;
#pragma unroll
        for (int i = 0; i < 8; i++) { int c = wcnt[i]; wcnt[i] = s; s += c; }
        wcnt[8] = s;
    }
    __syncthreads();
    int U = wcnt[8];
    if (t < n) {
        int cid = wcnt[w] + __popc(bits & ((2u << lane) - 1u)) - 1;
        if (cid < QMAX) {
            if (isb) uhp[cid] = hpack[t];
            atomicAdd(&ucnt[cid], 1.0f);
        }
    }
    __syncthreads();

    // build class Q vectors (2 per warp; rows >= U unused)
    float bq0 = bq[h * 64 + lane], bq1 = bq[h * 64 + 32 + lane];
#pragma unroll
    for (int uu = 0; uu < 2; uu++) {
        int u = w + uu * 8;
        if (u < U) {
            unsigned hp = uhp[u];
            float q0 = bq0, q1 = bq1;
#pragma unroll
            for (int j = 0; j < 8; j++) {
                int hh = (hp >> (3 * j)) & 7;
                const float* wb = &g_Wqb[h * 4096 + (j * 8 + hh) * 64];
                q0 += wb[lane];
                q1 += wb[lane + 32];
            }
            Qcls[u * 64 + lane] = q0;
            Qcls[u * 64 + 32 + lane] = q1;
        }
    }
    __syncthreads();

    int NC = (n + 31) >> 5;
    int T = U * NC;

    // score pass A: columns [0,32)
    for (int tk = w; tk < T; tk += 8) {
        int u = tk / NC, c2 = tk - u * NC;
        int s = c2 * 32 + lane;
        const float* Qu = &Qcls[u * 64];
        const float* Kr = &Ksh[s * KS2];
        float acc = 0.f;
#pragma unroll 8
        for (int c = 0; c < 32; c++) acc = fmaf(Qu[c], Kr[c], acc);
        if (s < n) scores[u * SSTR + s] = acc;
    }
    __syncthreads();

    // reload K columns [32,64)
    for (int idx = tid; idx < n * 32; idx += 256) {
        int s = idx >> 5, c = idx & 31;
        Ksh[s * KS2 + c] = g_K[(size_t)(off + s) * 512 + h * 64 + 32 + c];
    }
    __syncthreads();

    // score pass B
    for (int tk = w; tk < T; tk += 8) {
        int u = tk / NC, c2 = tk - u * NC;
        int s = c2 * 32 + lane;
        const float* Qu = &Qcls[u * 64 + 32];
        const float* Kr = &Ksh[s * KS2];
        float acc = 0.f;
#pragma unroll 8
        for (int c = 0; c < 32; c++) acc = fmaf(Qu[c], Kr[c], acc);
        if (s < n) scores[u * SSTR + s] += acc;
    }
    __syncthreads();

    // per-class softmax reduction
    for (int u = w; u < U; u += 8) {
        float m = -1e30f;
        for (int s = lane; s < n; s += 32) m = fmaxf(m, scores[u * SSTR + s]);
        m = warp_max(m) * 0.125f;
        float sum = 0.f;
        for (int s = lane; s < n; s += 32) sum += __expf(scores[u * SSTR + s] * 0.125f - m);
        sum = warp_sum(sum);
        if (lane == 0) { smu[u] = m; ssc[u] = ucnt[u] / sum; }
    }
    __syncthreads();

    // assemble avgw and write out
    if (tid < n) {
        float a = 0.f;
        for (int u = 0; u < U; u++)
            a += __expf(scores[u * SSTR + tid] * 0.125f - smu[u]) * ssc[u];
        g_avgw[((size_t)g * HEADS + h) * MAX_N + tid] = a / (float)ntrue;
    }
}

// ---------------- host launcher ----------------
extern "C" void kernel_launch(void* const* d_in, const int* in_sizes, int n_in,
                              void* d_out, int out_size)
{
    const float* x  = (const float*)d_in[0];
    const int*   bi = (const int*)  d_in[1];
    const float* gq = (const float*)d_in[2];
    const float* wq = (const float*)d_in[3];
    const float* bq = (const float*)d_in[4];
    const float* wk = (const float*)d_in[5];
    const float* bk = (const float*)d_in[6];
    const float* wv = (const float*)d_in[7];
    const float* bv = (const float*)d_in[8];
    const float* wo = (const float*)d_in[9];
    const float* bo = (const float*)d_in[10];
    const float* wp = (const float*)d_in[11];
    const float* bp = (const float*)d_in[12];
    float* out = (float*)d_out;

    void *pPooled, *pTmp;
    cudaGetSymbolAddress(&pPooled, g_pooled);
    cudaGetSymbolAddress(&pTmp, g_tmp);

    cudaFuncSetAttribute(kv_gemm_kernel, cudaFuncAttributeMaxDynamicSharedMemorySize, GEMM_SMEM);
    cudaFuncSetAttribute(attn_kernel, cudaFuncAttributeMaxDynamicSharedMemorySize, ATT_SMEM);

    // launch order: wqb(1), counts(2), convw(3), convx(4 = profiled slot)
    wqb_kernel<<<64, 512>>>(gq, wq);
    counts_kernel<<<1, 512>>>(bi, bk);
    convw_kernel<<<128, 512>>>(wk);
    convx_kernel<<<32768, 256>>>(x);

    kv_gemm_kernel<<<dim3(512 / BN, N_NODES / BM), 128, GEMM_SMEM>>>();

    attn_kernel<<<dim3(NUM_G, HEADS), 256, ATT_SMEM>>>(bq);

    xbar_kernel<<<dim3(NUM_G, XPARTS), 256>>>(x);
    vproj_kernel<<<dim3(NUM_G / 64, HEADS), 128>>>(wv, bv);

    sgemm32_kernel<false><<<dim3(16, 16), 128>>>(
        (const float*)pPooled, wo, bo, (float*)pTmp, NUM_G, DIM, DIM);
    sgemm32_kernel<true><<<dim3(16, 16), 128>>>(
        (const float*)pTmp, wp, bp, out, NUM_G, DIM, DIM);
}

// round 13
// speedup vs baseline: 1.0760x; 1.0760x over previous
#include <cuda_runtime.h>
#include <cuda_bf16.h>
#include <math.h>
#include <stdint.h>

#define N_NODES   65536
#define NUM_G     512
#define MAX_N     192
#define DIM       512
#define HEADS     8
#define DH        64
#define QMAX      16
#define KS2       33
#define XPARTS    4

#define BM 128
#define BN 128
#define NCHUNK 24
#define GEMM_SMEM (6 * 16384)

// ---------------- device scratch ----------------
__device__ float         g_K[(size_t)N_NODES * 512];
__device__ __nv_bfloat16 g_Xx[(size_t)N_NODES * 1024];
__device__ __nv_bfloat16 g_Wx[(size_t)512 * 1024];
__device__ float         g_bK[512];
__device__ float         g_Wqb[HEADS * 8 * 8 * 64];
__device__ float         g_avgw[NUM_G * HEADS * MAX_N];
__device__ float         g_xbar[XPARTS * NUM_G * HEADS * DIM];
__device__ float         g_pooled[NUM_G * DIM];
__device__ float         g_tmp[NUM_G * DIM];
__device__ int           g_counts[NUM_G];
__device__ int           g_offsets[NUM_G];

// ---------------- helpers ----------------
__device__ __forceinline__ uint32_t smem_u32(const void* p) {
    uint32_t a;
    asm("{ .reg .u64 t; cvta.to.shared.u64 t, %1; cvt.u32.u64 %0, t; }" : "=r"(a) : "l"(p));
    return a;
}
#define SWZ(b) ((b) ^ (((b) >> 3) & 0x70))

__device__ __forceinline__ void cp_async16(uint32_t dst, const void* src) {
    asm volatile("cp.async.cg.shared.global [%0], [%1], 16;" :: "r"(dst), "l"(src));
}
__device__ __forceinline__ void cp_commit() {
    asm volatile("cp.async.commit_group;" ::: "memory");
}
template <int N> __device__ __forceinline__ void cp_wait() {
    asm volatile("cp.async.wait_group %0;" :: "n"(N) : "memory");
}
__device__ __forceinline__ void ldm_x4(uint32_t& r0, uint32_t& r1, uint32_t& r2, uint32_t& r3,
                                       uint32_t addr) {
    asm volatile("ldmatrix.sync.aligned.m8n8.x4.shared.b16 {%0,%1,%2,%3}, [%4];"
                 : "=r"(r0), "=r"(r1), "=r"(r2), "=r"(r3) : "r"(addr));
}
__device__ __forceinline__ void mma_bf16(float& d0, float& d1, float& d2, float& d3,
                                         uint32_t a0, uint32_t a1, uint32_t a2, uint32_t a3,
                                         uint32_t b0, uint32_t b1) {
    asm volatile("mma.sync.aligned.m16n8k16.row.col.f32.bf16.bf16.f32 "
                 "{%0,%1,%2,%3}, {%4,%5,%6,%7}, {%8,%9}, {%0,%1,%2,%3};"
                 : "+f"(d0), "+f"(d1), "+f"(d2), "+f"(d3)
                 : "r"(a0), "r"(a1), "r"(a2), "r"(a3), "r"(b0), "r"(b1));
}

__device__ __forceinline__ void split4(float4 v, uint2* hi, uint2* lo) {
    __nv_bfloat16 h0 = __float2bfloat16_rn(v.x), h1 = __float2bfloat16_rn(v.y);
    __nv_bfloat16 h2 = __float2bfloat16_rn(v.z), h3 = __float2bfloat16_rn(v.w);
    __nv_bfloat16 l0 = __float2bfloat16_rn(v.x - __bfloat162float(h0));
    __nv_bfloat16 l1 = __float2bfloat16_rn(v.y - __bfloat162float(h1));
    __nv_bfloat16 l2 = __float2bfloat16_rn(v.z - __bfloat162float(h2));
    __nv_bfloat16 l3 = __float2bfloat16_rn(v.w - __bfloat162float(h3));
    hi->x = (uint32_t)__bfloat16_as_ushort(h0) | ((uint32_t)__bfloat16_as_ushort(h1) << 16);
    hi->y = (uint32_t)__bfloat16_as_ushort(h2) | ((uint32_t)__bfloat16_as_ushort(h3) << 16);
    lo->x = (uint32_t)__bfloat16_as_ushort(l0) | ((uint32_t)__bfloat16_as_ushort(l1) << 16);
    lo->y = (uint32_t)__bfloat16_as_ushort(l2) | ((uint32_t)__bfloat16_as_ushort(l3) << 16);
}

// ---------------- fused setup: wqb (0-63) + counts (64) + convw (65-192) ----
__global__ void __launch_bounds__(512) setup_kernel(
    const float* __restrict__ gq, const float* __restrict__ wq,
    const int* __restrict__ bidx, const float* __restrict__ bk,
    const float* __restrict__ wk)
{
    __shared__ float sbuf[512 + 64 * 65];
    int b = blockIdx.x;
    int tid = threadIdx.x;

    if (b < 64) {
        int h = b >> 3, j = b & 7;
        float* gqs = sbuf;
        float* wsh = sbuf + 512;
        gqs[tid] = gq[tid];
        for (int idx = tid; idx < 64 * 64; idx += 512) {
            int row = idx >> 6, cc = idx & 63;
            wsh[row * 65 + cc] = wq[(size_t)(h * 64 + row) * 512 + j * 64 + cc];
        }
        __syncthreads();
        int ol = tid & 63, hh = tid >> 6;
        float v = 0.f;
#pragma unroll 8
        for (int r = 0; r < 64; r++) v += gqs[hh * 64 + r] * wsh[ol * 65 + r];
        g_Wqb[h * 4096 + (j * 8 + hh) * 64 + ol] = v;
    } else if (b == 64) {
        int* lb = (int*)sbuf;
        int g = tid;
        int lo = 0, hi = N_NODES;
        while (lo < hi) { int mid = (lo + hi) >> 1; if (bidx[mid] < g) lo = mid + 1; else hi = mid; }
        lb[g] = lo;
        if (g == 0) lb[NUM_G] = N_NODES;
        __syncthreads();
        g_offsets[g] = lb[g];
        g_counts[g]  = lb[g + 1] - lb[g];
        g_bK[g] = bk[g];
    } else {
        int i = (b - 65) * 512 + tid;
        int r = i >> 7;
        int c4 = i & 127;
        float4 v = ((const float4*)wk)[(size_t)r * 128 + c4];
        uint2 hi, lo;
        split4(v, &hi, &lo);
        ((uint2*)(g_Wx + (size_t)r * 1024))[c4]       = hi;
        ((uint2*)(g_Wx + (size_t)r * 1024 + 512))[c4] = lo;
    }
}

// ---------------- convx ----------------
__global__ void __launch_bounds__(256) convx_kernel(const float* __restrict__ x) {
    size_t i = (size_t)blockIdx.x * 256 + threadIdx.x;
    float4 v = ((const float4*)x)[i];
    size_t r = i >> 7;
    int c4 = (int)(i & 127);
    uint2 hi, lo;
    split4(v, &hi, &lo);
    ((uint2*)(g_Xx + r * 1024))[c4]       = hi;
    ((uint2*)(g_Xx + r * 1024 + 512))[c4] = lo;
}

// ---------------- bf16 mma.sync K GEMM: 4 warps of 64x64 ----------------
__device__ __forceinline__ int a_index(int c) { return (c < 16) ? (c >> 1) : (c - 8); }

__device__ __forceinline__ void gemm_load_chunk(uint32_t sbase, int m0, int n0, int c, int tid) {
    int kq, kx, kw;
    bool loadA;
    if (c < 16) { kq = c >> 1; kx = kq * 64;       kw = kq * 64 + ((c & 1) ? 512 : 0); loadA = !(c & 1); }
    else        { kq = c - 16; kx = kq * 64 + 512; kw = kq * 64;                        loadA = true; }
    uint32_t sA = sbase + (uint32_t)(a_index(c) % 3) * 16384u;
    uint32_t sB = sbase + 49152u + (uint32_t)(c % 3) * 16384u;
    if (loadA) {
#pragma unroll
        for (int u = 0; u < 8; u++) {
            int idx = tid + u * 128;
            int row = idx >> 3;
            int cb = (idx & 7) * 16;
            cp_async16(sA + SWZ(row * 128 + cb),
                       (const char*)(g_Xx + (size_t)(m0 + row) * 1024 + kx) + cb);
        }
    }
#pragma unroll
    for (int u = 0; u < 8; u++) {
        int idx = tid + u * 128;
        int row = idx >> 3;
        int cb = (idx & 7) * 16;
        cp_async16(sB + SWZ(row * 128 + cb),
                   (const char*)(g_Wx + (size_t)(n0 + row) * 1024 + kw) + cb);
    }
    cp_commit();
}

__global__ void __launch_bounds__(128, 2) kv_gemm_kernel() {
    extern __shared__ char smem[];
    uint32_t sbase = smem_u32(smem);
    int tid = threadIdx.x;
    int lane = tid & 31, w = tid >> 5;
    int wm = w >> 1, wn = w & 1;
    int m0 = blockIdx.y * BM;
    int n0 = blockIdx.x * BN;

    float acc[4][8][4];
#pragma unroll
    for (int i = 0; i < 4; i++)
#pragma unroll
        for (int j = 0; j < 8; j++)
#pragma unroll
            for (int k = 0; k < 4; k++) acc[i][j][k] = 0.f;

    gemm_load_chunk(sbase, m0, n0, 0, tid);
    gemm_load_chunk(sbase, m0, n0, 1, tid);

    int lrow = ((lane >> 3) & 1) * 8 + (lane & 7);
    int lcol = ((lane >> 4) & 1) * 16;

    for (int c = 0; c < NCHUNK; c++) {
        if (c < NCHUNK - 1) cp_wait<1>(); else cp_wait<0>();
        __syncthreads();
        if (c + 2 < NCHUNK) gemm_load_chunk(sbase, m0, n0, c + 2, tid);

        uint32_t sA = sbase + (uint32_t)(a_index(c) % 3) * 16384u;
        uint32_t sB = sbase + 49152u + (uint32_t)(c % 3) * 16384u;

#pragma unroll
        for (int ks = 0; ks < 4; ks++) {
            uint32_t a[4][4], b[4][4];
#pragma unroll
            for (int mt = 0; mt < 4; mt++) {
                uint32_t addr = sA + SWZ((wm * 64 + mt * 16 + lrow) * 128 + ks * 32 + lcol);
                ldm_x4(a[mt][0], a[mt][1], a[mt][2], a[mt][3], addr);
            }
#pragma unroll
            for (int nt = 0; nt < 4; nt++) {
                uint32_t addr = sB + SWZ((wn * 64 + nt * 16 + lrow) * 128 + ks * 32 + lcol);
                ldm_x4(b[nt][0], b[nt][1], b[nt][2], b[nt][3], addr);
            }
#pragma unroll
            for (int mt = 0; mt < 4; mt++)
#pragma unroll
                for (int nt = 0; nt < 8; nt++) {
                    uint32_t b0 = b[nt >> 1][(nt & 1) ? 1 : 0];
                    uint32_t b1 = b[nt >> 1][(nt & 1) ? 3 : 2];
                    mma_bf16(acc[mt][nt][0], acc[mt][nt][1], acc[mt][nt][2], acc[mt][nt][3],
                             a[mt][0], a[mt][1], a[mt][2], a[mt][3], b0, b1);
                }
        }
    }

    int mrow = lane >> 2;
    int ncol = (lane & 3) * 2;
#pragma unroll
    for (int mt = 0; mt < 4; mt++) {
#pragma unroll
        for (int nt = 0; nt < 8; nt++) {
            int m = m0 + wm * 64 + mt * 16 + mrow;
            int n = n0 + wn * 64 + nt * 8 + ncol;
            float2 bias = *(const float2*)&g_bK[n];
            float2 v0 = make_float2(acc[mt][nt][0] + bias.x, acc[mt][nt][1] + bias.y);
            float2 v1 = make_float2(acc[mt][nt][2] + bias.x, acc[mt][nt][3] + bias.y);
            *(float2*)&g_K[(size_t)m * 512 + n] = v0;
            *(float2*)&g_K[(size_t)(m + 8) * 512 + n] = v1;
        }
    }
}

// ---------------- small SGEMM 32x32 tiles ----------------
template <bool RELU>
__global__ void __launch_bounds__(128) sgemm32_kernel(
    const float* __restrict__ A, const float* __restrict__ B,
    const float* __restrict__ bias, float* __restrict__ C,
    int M, int N, int K)
{
    __shared__ float As[16][32];
    __shared__ float Bs[16][32];
    int tid = threadIdx.x;
    int m0 = blockIdx.y * 32;
    int n0 = blockIdx.x * 32;
    int tr = tid >> 3, tc = tid & 7;
    int lr = tid >> 2;
    int lc = (tid & 3) * 4;
    float acc[2][4];
#pragma unroll
    for (int i = 0; i < 2; i++)
#pragma unroll
        for (int j = 0; j < 4; j++) acc[i][j] = 0.f;

    for (int k0 = 0; k0 < K; k0 += 16) {
        float4 a = *(const float4*)(A + (size_t)(m0 + lr) * K + k0 + lc);
        As[lc + 0][lr] = a.x; As[lc + 1][lr] = a.y; As[lc + 2][lr] = a.z; As[lc + 3][lr] = a.w;
        float4 b = *(const float4*)(B + (size_t)(n0 + lr) * K + k0 + lc);
        Bs[lc + 0][lr] = b.x; Bs[lc + 1][lr] = b.y; Bs[lc + 2][lr] = b.z; Bs[lc + 3][lr] = b.w;
        __syncthreads();
#pragma unroll
        for (int kk = 0; kk < 16; kk++) {
            float am[2], bn[4];
#pragma unroll
            for (int i = 0; i < 2; i++) am[i] = As[kk][tr * 2 + i];
#pragma unroll
            for (int j = 0; j < 4; j++) bn[j] = Bs[kk][tc * 4 + j];
#pragma unroll
            for (int i = 0; i < 2; i++)
#pragma unroll
                for (int j = 0; j < 4; j++) acc[i][j] = fmaf(am[i], bn[j], acc[i][j]);
        }
        __syncthreads();
    }
#pragma unroll
    for (int i = 0; i < 2; i++) {
        int m = m0 + tr * 2 + i;
#pragma unroll
        for (int j = 0; j < 4; j++) {
            int n = n0 + tc * 4 + j;
            float v = acc[i][j] + bias[n];
            if (RELU) v = fmaxf(v, 0.f);
            C[(size_t)m * N + n] = v;
        }
    }
}

// ---------------- V projection on xbar (sums XPARTS partials) ----------------
__global__ void __launch_bounds__(128) vproj_kernel(const float* __restrict__ wv,
                                                    const float* __restrict__ bv)
{
    __shared__ float As[16][64];
    __shared__ float Bs[16][64];
    int tid = threadIdx.x;
    int h = blockIdx.y;
    int m0 = blockIdx.x * 64;
    int tr = tid >> 3, tc = tid & 7;
    int lr = tid >> 2;
    int lc = (tid & 3) * 4;
    float acc[4][8];
#pragma unroll
    for (int i = 0; i < 4; i++)
#pragma unroll
        for (int j = 0; j < 8; j++) acc[i][j] = 0.f;

    const size_t PSTRIDE = (size_t)NUM_G * HEADS * DIM;

    for (int k0 = 0; k0 < 512; k0 += 16) {
#pragma unroll
        for (int p = 0; p < 2; p++) {
            int r = lr + 32 * p;
            size_t base = ((size_t)(m0 + r) * 8 + h) * 512 + k0 + lc;
            float4 a = *(const float4*)(g_xbar + base);
#pragma unroll
            for (int q = 1; q < XPARTS; q++) {
                float4 a2 = *(const float4*)(g_xbar + q * PSTRIDE + base);
                a.x += a2.x; a.y += a2.y; a.z += a2.z; a.w += a2.w;
            }
            As[lc + 0][r] = a.x; As[lc + 1][r] = a.y; As[lc + 2][r] = a.z; As[lc + 3][r] = a.w;
            float4 b = *(const float4*)(wv + (size_t)(h * 64 + r) * 512 + k0 + lc);
            Bs[lc + 0][r] = b.x; Bs[lc + 1][r] = b.y; Bs[lc + 2][r] = b.z; Bs[lc + 3][r] = b.w;
        }
        __syncthreads();
#pragma unroll
        for (int kk = 0; kk < 16; kk++) {
            float am[4], bn[8];
#pragma unroll
            for (int i = 0; i < 4; i++) am[i] = As[kk][tr * 4 + i];
#pragma unroll
            for (int j = 0; j < 8; j++) bn[j] = Bs[kk][tc * 8 + j];
#pragma unroll
            for (int i = 0; i < 4; i++)
#pragma unroll
                for (int j = 0; j < 8; j++) acc[i][j] = fmaf(am[i], bn[j], acc[i][j]);
        }
        __syncthreads();
    }
#pragma unroll
    for (int i = 0; i < 4; i++) {
        int m = m0 + tr * 4 + i;
        int cnt = g_counts[m];
        int nn = cnt < MAX_N ? cnt : MAX_N;
        float scale = (cnt > 0) ? (float)nn / (float)cnt : 0.f;
#pragma unroll
        for (int j = 0; j < 8; j++) {
            int nc = tc * 8 + j;
            g_pooled[(size_t)m * DIM + h * 64 + nc] = acc[i][j] + scale * bv[h * 64 + nc];
        }
    }
}

// ---------------- xbar: s-split partial weighted x sums ----------------
__global__ void __launch_bounds__(256) xbar_kernel(const float* __restrict__ x) {
    int g = blockIdx.x;
    int part = blockIdx.y;
    int ntrue = g_counts[g];
    int off = g_offsets[g];
    int n = ntrue < MAX_N ? ntrue : MAX_N;
    __shared__ float aw[HEADS * MAX_N];
    int tid = threadIdx.x;

    float acc[HEADS][2];
#pragma unroll
    for (int h = 0; h < HEADS; h++) { acc[h][0] = 0.f; acc[h][1] = 0.f; }

    if (n > 0) {
#pragma unroll
        for (int h = 0; h < HEADS; h++)
            for (int s = tid; s < n; s += 256)
                aw[h * MAX_N + s] = g_avgw[((size_t)g * HEADS + h) * MAX_N + s];
        __syncthreads();

        const float* xb = x + (size_t)off * 512;
        for (int s = part; s < n; s += XPARTS) {
            float x0 = xb[(size_t)s * 512 + tid];
            float x1 = xb[(size_t)s * 512 + tid + 256];
#pragma unroll
            for (int h = 0; h < HEADS; h++) {
                float wv = aw[h * MAX_N + s];
                acc[h][0] = fmaf(wv, x0, acc[h][0]);
                acc[h][1] = fmaf(wv, x1, acc[h][1]);
            }
        }
    }
    size_t pbase = (size_t)part * NUM_G * HEADS * DIM;
#pragma unroll
    for (int h = 0; h < HEADS; h++) {
        g_xbar[pbase + ((size_t)g * HEADS + h) * 512 + tid]       = acc[h][0];
        g_xbar[pbase + ((size_t)g * HEADS + h) * 512 + tid + 256] = acc[h][1];
    }
}

// ---------------- attention: Q-class + two-pass K (round-11 version) ----------------
__device__ __forceinline__ float warp_max(float v) {
#pragma unroll
    for (int o = 16; o > 0; o >>= 1) v = fmaxf(v, __shfl_xor_sync(0xffffffffu, v, o));
    return v;
}
__device__ __forceinline__ float warp_sum(float v) {
#pragma unroll
    for (int o = 16; o > 0; o >>= 1) v += __shfl_xor_sync(0xffffffffu, v, o);
    return v;
}

template <int NK>
__device__ void attn_body2(int n, int lane, int w, int off, int h, int tid,
                           float* __restrict__ Ksh,
                           const float* __restrict__ Qcls,
                           const float* __restrict__ ucnt,
                           float* __restrict__ avgw)
{
    float sc0[NK], sc1[NK];
#pragma unroll
    for (int k = 0; k < NK; k++) { sc0[k] = 0.f; sc1[k] = 0.f; }
    const float* Q0 = &Qcls[w * 64];
    const float* Q1 = &Qcls[(w + 8) * 64];

    for (int c = 0; c < 32; c++) {
        float q0 = Q0[c], q1 = Q1[c];
        float kv[NK];
#pragma unroll
        for (int k = 0; k < NK; k++) kv[k] = Ksh[(lane + 32 * k) * KS2 + c];
#pragma unroll
        for (int k = 0; k < NK; k++) { sc0[k] = fmaf(q0, kv[k], sc0[k]); sc1[k] = fmaf(q1, kv[k], sc1[k]); }
    }
    __syncthreads();
    for (int idx = tid; idx < n * 32; idx += 256) {
        int s = idx >> 5, c = idx & 31;
        Ksh[s * KS2 + c] = g_K[(size_t)(off + s) * 512 + h * 64 + 32 + c];
    }
    __syncthreads();
    for (int c = 0; c < 32; c++) {
        float q0 = Q0[32 + c], q1 = Q1[32 + c];
        float kv[NK];
#pragma unroll
        for (int k = 0; k < NK; k++) kv[k] = Ksh[(lane + 32 * k) * KS2 + c];
#pragma unroll
        for (int k = 0; k < NK; k++) { sc0[k] = fmaf(q0, kv[k], sc0[k]); sc1[k] = fmaf(q1, kv[k], sc1[k]); }
    }

    float aacc[NK];
#pragma unroll
    for (int k = 0; k < NK; k++) aacc[k] = 0.f;

#pragma unroll
    for (int uu = 0; uu < 2; uu++) {
        float* sc = uu ? sc1 : sc0;
        float cnt = ucnt[uu ? (w + 8) : w];
        float m = -1e30f;
#pragma unroll
        for (int k = 0; k < NK; k++) {
            float v = (lane + 32 * k < n) ? sc[k] * 0.125f : -1e30f;
            sc[k] = v;
            m = fmaxf(m, v);
        }
        m = warp_max(m);
        float lsum = 0.f;
#pragma unroll
        for (int k = 0; k < NK; k++) {
            float e = __expf(sc[k] - m);
            sc[k] = e;
            lsum += e;
        }
        float scale = cnt / warp_sum(lsum);
#pragma unroll
        for (int k = 0; k < NK; k++) aacc[k] += sc[k] * scale;
    }
#pragma unroll
    for (int k = 0; k < NK; k++) {
        int s = lane + 32 * k;
        if (s < n) atomicAdd(&avgw[s], aacc[k]);
    }
}

#define ATT_SMEM ((6336 + 1024 + 192 + 192 + 16 + 16 + 12) * 4)

__global__ void __launch_bounds__(256) attn_kernel(const float* __restrict__ bq)
{
    int g = blockIdx.x, h = blockIdx.y;
    int ntrue = g_counts[g];
    int off = g_offsets[g];
    extern __shared__ float sm[];
    float*    Ksh   = sm;
    float*    Qcls  = Ksh + MAX_N * KS2;
    float*    avgw  = Qcls + QMAX * 64;
    unsigned* hpack = (unsigned*)(avgw + MAX_N);
    unsigned* uhp   = hpack + MAX_N;
    float*    ucnt  = (float*)(uhp + QMAX);
    int*      wcnt  = (int*)(ucnt + QMAX);

    int tid = threadIdx.x, lane = tid & 31, w = tid >> 5;

    if (ntrue <= 0) return;
    int n = ntrue < MAX_N ? ntrue : MAX_N;

    for (int idx = tid; idx < n * 32; idx += 256) {
        int s = idx >> 5, c = idx & 31;
        Ksh[s * KS2 + c] = g_K[(size_t)(off + s) * 512 + h * 64 + c];
    }
    for (int idx = tid; idx < MAX_N; idx += 256) avgw[idx] = 0.f;
    if (tid < QMAX) { ucnt[tid] = 0.f; uhp[tid] = 0u; }
    for (int t = tid; t < n; t += 256) {
        unsigned p = 0;
#pragma unroll
        for (int j = 0; j < 8; j++) {
            unsigned hh = (unsigned)(8 * t + j) / (unsigned)ntrue;
            if (hh > 7) hh = 7;
            p |= hh << (3 * j);
        }
        hpack[t] = p;
    }
    __syncthreads();

    int t = tid;
    int isb = (t < n) && (t == 0 || hpack[t] != hpack[t - 1]);
    unsigned bits = __ballot_sync(0xffffffffu, isb);
    if (lane == 31) wcnt[w] = __popc(bits);
    __syncthreads();
    if (tid == 0) {
        int s = 0;
#pragma unroll
        for (int i = 0; i < 8; i++) { int c = wcnt[i]; wcnt[i] = s; s += c; }
        wcnt[8] = s;
    }
    __syncthreads();
    int U = wcnt[8];
    if (t < n) {
        int cid = wcnt[w] + __popc(bits & ((2u << lane) - 1u)) - 1;
        if (cid < QMAX) {
            if (isb) uhp[cid] = hpack[t];
            atomicAdd(&ucnt[cid], 1.0f);
        }
    }
    __syncthreads();

    float bq0 = bq[h * 64 + lane], bq1 = bq[h * 64 + 32 + lane];
#pragma unroll
    for (int uu = 0; uu < 2; uu++) {
        int u = w + uu * 8;
        float q0 = 0.f, q1 = 0.f;
        if (u < U) {
            unsigned hp = uhp[u];
            q0 = bq0; q1 = bq1;
#pragma unroll
            for (int j = 0; j < 8; j++) {
                int hh = (hp >> (3 * j)) & 7;
                const float* wb = &g_Wqb[h * 4096 + (j * 8 + hh) * 64];
                q0 += wb[lane];
                q1 += wb[lane + 32];
            }
        }
        Qcls[u * 64 + lane] = q0;
        Qcls[u * 64 + 32 + lane] = q1;
    }
    __syncthreads();

    int nk = (n + 31) >> 5;
    switch (nk) {
        case 1: attn_body2<1>(n, lane, w, off, h, tid, Ksh, Qcls, ucnt, avgw); break;
        case 2: attn_body2<2>(n, lane, w, off, h, tid, Ksh, Qcls, ucnt, avgw); break;
        case 3: attn_body2<3>(n, lane, w, off, h, tid, Ksh, Qcls, ucnt, avgw); break;
        case 4: attn_body2<4>(n, lane, w, off, h, tid, Ksh, Qcls, ucnt, avgw); break;
        case 5: attn_body2<5>(n, lane, w, off, h, tid, Ksh, Qcls, ucnt, avgw); break;
        default: attn_body2<6>(n, lane, w, off, h, tid, Ksh, Qcls, ucnt, avgw); break;
    }
    __syncthreads();

    float inv = 1.0f / (float)ntrue;
    for (int s = tid; s < n; s += 256)
        g_avgw[((size_t)g * HEADS + h) * MAX_N + s] = avgw[s] * inv;
}

// ---------------- host launcher ----------------
extern "C" void kernel_launch(void* const* d_in, const int* in_sizes, int n_in,
                              void* d_out, int out_size)
{
    const float* x  = (const float*)d_in[0];
    const int*   bi = (const int*)  d_in[1];
    const float* gq = (const float*)d_in[2];
    const float* wq = (const float*)d_in[3];
    const float* bq = (const float*)d_in[4];
    const float* wk = (const float*)d_in[5];
    const float* bk = (const float*)d_in[6];
    const float* wv = (const float*)d_in[7];
    const float* bv = (const float*)d_in[8];
    const float* wo = (const float*)d_in[9];
    const float* bo = (const float*)d_in[10];
    const float* wp = (const float*)d_in[11];
    const float* bp = (const float*)d_in[12];
    float* out = (float*)d_out;

    void *pPooled, *pTmp;
    cudaGetSymbolAddress(&pPooled, g_pooled);
    cudaGetSymbolAddress(&pTmp, g_tmp);

    cudaFuncSetAttribute(kv_gemm_kernel, cudaFuncAttributeMaxDynamicSharedMemorySize, GEMM_SMEM);

    // launch order: setup(1), convx(2), kv_gemm(3), attn(4 = profiled slot)
    setup_kernel<<<193, 512>>>(gq, wq, bi, bk, wk);
    convx_kernel<<<32768, 256>>>(x);

    kv_gemm_kernel<<<dim3(512 / BN, N_NODES / BM), 128, GEMM_SMEM>>>();

    attn_kernel<<<dim3(NUM_G, HEADS), 256, ATT_SMEM>>>(bq);

    xbar_kernel<<<dim3(NUM_G, XPARTS), 256>>>(x);
    vproj_kernel<<<dim3(NUM_G / 64, HEADS), 128>>>(wv, bv);

    sgemm32_kernel<false><<<dim3(16, 16), 128>>>(
        (const float*)pPooled, wo, bo, (float*)pTmp, NUM_G, DIM, DIM);
    sgemm32_kernel<true><<<dim3(16, 16), 128>>>(
        (const float*)pTmp, wp, bp, out, NUM_G, DIM, DIM);
}

// round 14
// speedup vs baseline: 1.0875x; 1.0106x over previous
#include <cuda_runtime.h>
#include <cuda_bf16.h>
#include <math.h>
#include <stdint.h>

#define N_NODES   65536
#define NUM_G     512
#define MAX_N     192
#define DIM       512
#define HEADS     8
#define DH        64
#define QMAX      16
#define KS2       33
#define XPARTS    4

#define BM 128
#define BN 128
#define NCHUNK 24
#define GEMM_SMEM (6 * 16384)

// ---------------- device scratch ----------------
__device__ float         g_K[(size_t)N_NODES * 512];
__device__ __nv_bfloat16 g_Xx[(size_t)N_NODES * 1024];
__device__ __nv_bfloat16 g_Wx[(size_t)512 * 1024];
__device__ float         g_bK[512];
__device__ float         g_Wqb[HEADS * 8 * 8 * 64];
__device__ float         g_avgw[NUM_G * HEADS * MAX_N];
__device__ float         g_xbar[XPARTS * NUM_G * HEADS * DIM];
__device__ float         g_pooled[NUM_G * DIM];
__device__ float         g_tmp[NUM_G * DIM];
__device__ int           g_counts[NUM_G];
__device__ int           g_offsets[NUM_G];

// ---------------- helpers ----------------
__device__ __forceinline__ uint32_t smem_u32(const void* p) {
    uint32_t a;
    asm("{ .reg .u64 t; cvta.to.shared.u64 t, %1; cvt.u32.u64 %0, t; }" : "=r"(a) : "l"(p));
    return a;
}
#define SWZ(b) ((b) ^ (((b) >> 3) & 0x70))

__device__ __forceinline__ void cp_async16(uint32_t dst, const void* src) {
    asm volatile("cp.async.cg.shared.global [%0], [%1], 16;" :: "r"(dst), "l"(src));
}
__device__ __forceinline__ void cp_commit() {
    asm volatile("cp.async.commit_group;" ::: "memory");
}
template <int N> __device__ __forceinline__ void cp_wait() {
    asm volatile("cp.async.wait_group %0;" :: "n"(N) : "memory");
}
__device__ __forceinline__ void ldm_x4(uint32_t& r0, uint32_t& r1, uint32_t& r2, uint32_t& r3,
                                       uint32_t addr) {
    asm volatile("ldmatrix.sync.aligned.m8n8.x4.shared.b16 {%0,%1,%2,%3}, [%4];"
                 : "=r"(r0), "=r"(r1), "=r"(r2), "=r"(r3) : "r"(addr));
}
__device__ __forceinline__ void mma_bf16(float& d0, float& d1, float& d2, float& d3,
                                         uint32_t a0, uint32_t a1, uint32_t a2, uint32_t a3,
                                         uint32_t b0, uint32_t b1) {
    asm volatile("mma.sync.aligned.m16n8k16.row.col.f32.bf16.bf16.f32 "
                 "{%0,%1,%2,%3}, {%4,%5,%6,%7}, {%8,%9}, {%0,%1,%2,%3};"
                 : "+f"(d0), "+f"(d1), "+f"(d2), "+f"(d3)
                 : "r"(a0), "r"(a1), "r"(a2), "r"(a3), "r"(b0), "r"(b1));
}

__device__ __forceinline__ void split4(float4 v, uint2* hi, uint2* lo) {
    __nv_bfloat16 h0 = __float2bfloat16_rn(v.x), h1 = __float2bfloat16_rn(v.y);
    __nv_bfloat16 h2 = __float2bfloat16_rn(v.z), h3 = __float2bfloat16_rn(v.w);
    __nv_bfloat16 l0 = __float2bfloat16_rn(v.x - __bfloat162float(h0));
    __nv_bfloat16 l1 = __float2bfloat16_rn(v.y - __bfloat162float(h1));
    __nv_bfloat16 l2 = __float2bfloat16_rn(v.z - __bfloat162float(h2));
    __nv_bfloat16 l3 = __float2bfloat16_rn(v.w - __bfloat162float(h3));
    hi->x = (uint32_t)__bfloat16_as_ushort(h0) | ((uint32_t)__bfloat16_as_ushort(h1) << 16);
    hi->y = (uint32_t)__bfloat16_as_ushort(h2) | ((uint32_t)__bfloat16_as_ushort(h3) << 16);
    lo->x = (uint32_t)__bfloat16_as_ushort(l0) | ((uint32_t)__bfloat16_as_ushort(l1) << 16);
    lo->y = (uint32_t)__bfloat16_as_ushort(l2) | ((uint32_t)__bfloat16_as_ushort(l3) << 16);
}

// ---------------- fused setup: wqb(0-63) + counts(64) + convw(65-192) + convx(193+) ----
__global__ void __launch_bounds__(512) setup_kernel(
    const float* __restrict__ gq, const float* __restrict__ wq,
    const int* __restrict__ bidx, const float* __restrict__ bk,
    const float* __restrict__ wk, const float* __restrict__ x)
{
    __shared__ float sbuf[512 + 64 * 65];
    int b = blockIdx.x;
    int tid = threadIdx.x;

    if (b >= 193) {                      // ---- convx: bulk fp32->bf16 hi/lo ----
        size_t i = (size_t)(b - 193) * 512 + tid;
        float4 v = ((const float4*)x)[i];
        size_t r = i >> 7;
        int c4 = (int)(i & 127);
        uint2 hi, lo;
        split4(v, &hi, &lo);
        ((uint2*)(g_Xx + r * 1024))[c4]       = hi;
        ((uint2*)(g_Xx + r * 1024 + 512))[c4] = lo;
    } else if (b < 64) {                 // ---- wqb ----
        int h = b >> 3, j = b & 7;
        float* gqs = sbuf;
        float* wsh = sbuf + 512;
        gqs[tid] = gq[tid];
        for (int idx = tid; idx < 64 * 64; idx += 512) {
            int row = idx >> 6, cc = idx & 63;
            wsh[row * 65 + cc] = wq[(size_t)(h * 64 + row) * 512 + j * 64 + cc];
        }
        __syncthreads();
        int ol = tid & 63, hh = tid >> 6;
        float v = 0.f;
#pragma unroll 8
        for (int r = 0; r < 64; r++) v += gqs[hh * 64 + r] * wsh[ol * 65 + r];
        g_Wqb[h * 4096 + (j * 8 + hh) * 64 + ol] = v;
    } else if (b == 64) {                // ---- counts + bias ----
        int* lb = (int*)sbuf;
        int g = tid;
        int lo = 0, hi = N_NODES;
        while (lo < hi) { int mid = (lo + hi) >> 1; if (bidx[mid] < g) lo = mid + 1; else hi = mid; }
        lb[g] = lo;
        if (g == 0) lb[NUM_G] = N_NODES;
        __syncthreads();
        g_offsets[g] = lb[g];
        g_counts[g]  = lb[g + 1] - lb[g];
        g_bK[g] = bk[g];
    } else {                             // ---- convw ----
        int i = (b - 65) * 512 + tid;
        int r = i >> 7;
        int c4 = i & 127;
        float4 v = ((const float4*)wk)[(size_t)r * 128 + c4];
        uint2 hi, lo;
        split4(v, &hi, &lo);
        ((uint2*)(g_Wx + (size_t)r * 1024))[c4]       = hi;
        ((uint2*)(g_Wx + (size_t)r * 1024 + 512))[c4] = lo;
    }
}

// ---------------- bf16 mma.sync K GEMM: 4 warps of 64x64 ----------------
__device__ __forceinline__ int a_index(int c) { return (c < 16) ? (c >> 1) : (c - 8); }

__device__ __forceinline__ void gemm_load_chunk(uint32_t sbase, int m0, int n0, int c, int tid) {
    int kq, kx, kw;
    bool loadA;
    if (c < 16) { kq = c >> 1; kx = kq * 64;       kw = kq * 64 + ((c & 1) ? 512 : 0); loadA = !(c & 1); }
    else        { kq = c - 16; kx = kq * 64 + 512; kw = kq * 64;                        loadA = true; }
    uint32_t sA = sbase + (uint32_t)(a_index(c) % 3) * 16384u;
    uint32_t sB = sbase + 49152u + (uint32_t)(c % 3) * 16384u;
    if (loadA) {
#pragma unroll
        for (int u = 0; u < 8; u++) {
            int idx = tid + u * 128;
            int row = idx >> 3;
            int cb = (idx & 7) * 16;
            cp_async16(sA + SWZ(row * 128 + cb),
                       (const char*)(g_Xx + (size_t)(m0 + row) * 1024 + kx) + cb);
        }
    }
#pragma unroll
    for (int u = 0; u < 8; u++) {
        int idx = tid + u * 128;
        int row = idx >> 3;
        int cb = (idx & 7) * 16;
        cp_async16(sB + SWZ(row * 128 + cb),
                   (const char*)(g_Wx + (size_t)(n0 + row) * 1024 + kw) + cb);
    }
    cp_commit();
}

__global__ void __launch_bounds__(128, 2) kv_gemm_kernel() {
    extern __shared__ char smem[];
    uint32_t sbase = smem_u32(smem);
    int tid = threadIdx.x;
    int lane = tid & 31, w = tid >> 5;
    int wm = w >> 1, wn = w & 1;
    int m0 = blockIdx.y * BM;
    int n0 = blockIdx.x * BN;

    float acc[4][8][4];
#pragma unroll
    for (int i = 0; i < 4; i++)
#pragma unroll
        for (int j = 0; j < 8; j++)
#pragma unroll
            for (int k = 0; k < 4; k++) acc[i][j][k] = 0.f;

    gemm_load_chunk(sbase, m0, n0, 0, tid);
    gemm_load_chunk(sbase, m0, n0, 1, tid);

    int lrow = ((lane >> 3) & 1) * 8 + (lane & 7);
    int lcol = ((lane >> 4) & 1) * 16;

    for (int c = 0; c < NCHUNK; c++) {
        if (c < NCHUNK - 1) cp_wait<1>(); else cp_wait<0>();
        __syncthreads();
        if (c + 2 < NCHUNK) gemm_load_chunk(sbase, m0, n0, c + 2, tid);

        uint32_t sA = sbase + (uint32_t)(a_index(c) % 3) * 16384u;
        uint32_t sB = sbase + 49152u + (uint32_t)(c % 3) * 16384u;

#pragma unroll
        for (int ks = 0; ks < 4; ks++) {
            uint32_t a[4][4], b[4][4];
#pragma unroll
            for (int mt = 0; mt < 4; mt++) {
                uint32_t addr = sA + SWZ((wm * 64 + mt * 16 + lrow) * 128 + ks * 32 + lcol);
                ldm_x4(a[mt][0], a[mt][1], a[mt][2], a[mt][3], addr);
            }
#pragma unroll
            for (int nt = 0; nt < 4; nt++) {
                uint32_t addr = sB + SWZ((wn * 64 + nt * 16 + lrow) * 128 + ks * 32 + lcol);
                ldm_x4(b[nt][0], b[nt][1], b[nt][2], b[nt][3], addr);
            }
#pragma unroll
            for (int mt = 0; mt < 4; mt++)
#pragma unroll
                for (int nt = 0; nt < 8; nt++) {
                    uint32_t b0 = b[nt >> 1][(nt & 1) ? 1 : 0];
                    uint32_t b1 = b[nt >> 1][(nt & 1) ? 3 : 2];
                    mma_bf16(acc[mt][nt][0], acc[mt][nt][1], acc[mt][nt][2], acc[mt][nt][3],
                             a[mt][0], a[mt][1], a[mt][2], a[mt][3], b0, b1);
                }
        }
    }

    int mrow = lane >> 2;
    int ncol = (lane & 3) * 2;
#pragma unroll
    for (int mt = 0; mt < 4; mt++) {
#pragma unroll
        for (int nt = 0; nt < 8; nt++) {
            int m = m0 + wm * 64 + mt * 16 + mrow;
            int n = n0 + wn * 64 + nt * 8 + ncol;
            float2 bias = *(const float2*)&g_bK[n];
            float2 v0 = make_float2(acc[mt][nt][0] + bias.x, acc[mt][nt][1] + bias.y);
            float2 v1 = make_float2(acc[mt][nt][2] + bias.x, acc[mt][nt][3] + bias.y);
            *(float2*)&g_K[(size_t)m * 512 + n] = v0;
            *(float2*)&g_K[(size_t)(m + 8) * 512 + n] = v1;
        }
    }
}

// ---------------- small SGEMM 32x32 tiles ----------------
template <bool RELU>
__global__ void __launch_bounds__(128) sgemm32_kernel(
    const float* __restrict__ A, const float* __restrict__ B,
    const float* __restrict__ bias, float* __restrict__ C,
    int M, int N, int K)
{
    __shared__ float As[16][32];
    __shared__ float Bs[16][32];
    int tid = threadIdx.x;
    int m0 = blockIdx.y * 32;
    int n0 = blockIdx.x * 32;
    int tr = tid >> 3, tc = tid & 7;
    int lr = tid >> 2;
    int lc = (tid & 3) * 4;
    float acc[2][4];
#pragma unroll
    for (int i = 0; i < 2; i++)
#pragma unroll
        for (int j = 0; j < 4; j++) acc[i][j] = 0.f;

    for (int k0 = 0; k0 < K; k0 += 16) {
        float4 a = *(const float4*)(A + (size_t)(m0 + lr) * K + k0 + lc);
        As[lc + 0][lr] = a.x; As[lc + 1][lr] = a.y; As[lc + 2][lr] = a.z; As[lc + 3][lr] = a.w;
        float4 b = *(const float4*)(B + (size_t)(n0 + lr) * K + k0 + lc);
        Bs[lc + 0][lr] = b.x; Bs[lc + 1][lr] = b.y; Bs[lc + 2][lr] = b.z; Bs[lc + 3][lr] = b.w;
        __syncthreads();
#pragma unroll
        for (int kk = 0; kk < 16; kk++) {
            float am[2], bn[4];
#pragma unroll
            for (int i = 0; i < 2; i++) am[i] = As[kk][tr * 2 + i];
#pragma unroll
            for (int j = 0; j < 4; j++) bn[j] = Bs[kk][tc * 4 + j];
#pragma unroll
            for (int i = 0; i < 2; i++)
#pragma unroll
                for (int j = 0; j < 4; j++) acc[i][j] = fmaf(am[i], bn[j], acc[i][j]);
        }
        __syncthreads();
    }
#pragma unroll
    for (int i = 0; i < 2; i++) {
        int m = m0 + tr * 2 + i;
#pragma unroll
        for (int j = 0; j < 4; j++) {
            int n = n0 + tc * 4 + j;
            float v = acc[i][j] + bias[n];
            if (RELU) v = fmaxf(v, 0.f);
            C[(size_t)m * N + n] = v;
        }
    }
}

// ---------------- V projection on xbar ----------------
__global__ void __launch_bounds__(128) vproj_kernel(const float* __restrict__ wv,
                                                    const float* __restrict__ bv)
{
    __shared__ float As[16][64];
    __shared__ float Bs[16][64];
    int tid = threadIdx.x;
    int h = blockIdx.y;
    int m0 = blockIdx.x * 64;
    int tr = tid >> 3, tc = tid & 7;
    int lr = tid >> 2;
    int lc = (tid & 3) * 4;
    float acc[4][8];
#pragma unroll
    for (int i = 0; i < 4; i++)
#pragma unroll
        for (int j = 0; j < 8; j++) acc[i][j] = 0.f;

    const size_t PSTRIDE = (size_t)NUM_G * HEADS * DIM;

    for (int k0 = 0; k0 < 512; k0 += 16) {
#pragma unroll
        for (int p = 0; p < 2; p++) {
            int r = lr + 32 * p;
            size_t base = ((size_t)(m0 + r) * 8 + h) * 512 + k0 + lc;
            float4 a = *(const float4*)(g_xbar + base);
#pragma unroll
            for (int q = 1; q < XPARTS; q++) {
                float4 a2 = *(const float4*)(g_xbar + q * PSTRIDE + base);
                a.x += a2.x; a.y += a2.y; a.z += a2.z; a.w += a2.w;
            }
            As[lc + 0][r] = a.x; As[lc + 1][r] = a.y; As[lc + 2][r] = a.z; As[lc + 3][r] = a.w;
            float4 b = *(const float4*)(wv + (size_t)(h * 64 + r) * 512 + k0 + lc);
            Bs[lc + 0][r] = b.x; Bs[lc + 1][r] = b.y; Bs[lc + 2][r] = b.z; Bs[lc + 3][r] = b.w;
        }
        __syncthreads();
#pragma unroll
        for (int kk = 0; kk < 16; kk++) {
            float am[4], bn[8];
#pragma unroll
            for (int i = 0; i < 4; i++) am[i] = As[kk][tr * 4 + i];
#pragma unroll
            for (int j = 0; j < 8; j++) bn[j] = Bs[kk][tc * 8 + j];
#pragma unroll
            for (int i = 0; i < 4; i++)
#pragma unroll
                for (int j = 0; j < 8; j++) acc[i][j] = fmaf(am[i], bn[j], acc[i][j]);
        }
        __syncthreads();
    }
#pragma unroll
    for (int i = 0; i < 4; i++) {
        int m = m0 + tr * 4 + i;
        int cnt = g_counts[m];
        int nn = cnt < MAX_N ? cnt : MAX_N;
        float scale = (cnt > 0) ? (float)nn / (float)cnt : 0.f;
#pragma unroll
        for (int j = 0; j < 8; j++) {
            int nc = tc * 8 + j;
            g_pooled[(size_t)m * DIM + h * 64 + nc] = acc[i][j] + scale * bv[h * 64 + nc];
        }
    }
}

// ---------------- xbar: s-split partial weighted x sums (profiled slot) ----------------
__global__ void __launch_bounds__(256) xbar_kernel(const float* __restrict__ x) {
    int g = blockIdx.x;
    int part = blockIdx.y;
    int ntrue = g_counts[g];
    int off = g_offsets[g];
    int n = ntrue < MAX_N ? ntrue : MAX_N;
    __shared__ float aw[HEADS * MAX_N];
    int tid = threadIdx.x;

    float acc[HEADS][2];
#pragma unroll
    for (int h = 0; h < HEADS; h++) { acc[h][0] = 0.f; acc[h][1] = 0.f; }

    if (n > 0) {
#pragma unroll
        for (int h = 0; h < HEADS; h++)
            for (int s = tid; s < n; s += 256)
                aw[h * MAX_N + s] = g_avgw[((size_t)g * HEADS + h) * MAX_N + s];
        __syncthreads();

        const float* xb = x + (size_t)off * 512;
        for (int s = part; s < n; s += XPARTS) {
            float x0 = xb[(size_t)s * 512 + tid];
            float x1 = xb[(size_t)s * 512 + tid + 256];
#pragma unroll
            for (int h = 0; h < HEADS; h++) {
                float wv = aw[h * MAX_N + s];
                acc[h][0] = fmaf(wv, x0, acc[h][0]);
                acc[h][1] = fmaf(wv, x1, acc[h][1]);
            }
        }
    }
    size_t pbase = (size_t)part * NUM_G * HEADS * DIM;
#pragma unroll
    for (int h = 0; h < HEADS; h++) {
        g_xbar[pbase + ((size_t)g * HEADS + h) * 512 + tid]       = acc[h][0];
        g_xbar[pbase + ((size_t)g * HEADS + h) * 512 + tid + 256] = acc[h][1];
    }
}

// ---------------- attention: Q-class + two-pass K + dead-class skip ----------------
__device__ __forceinline__ float warp_max(float v) {
#pragma unroll
    for (int o = 16; o > 0; o >>= 1) v = fmaxf(v, __shfl_xor_sync(0xffffffffu, v, o));
    return v;
}
__device__ __forceinline__ float warp_sum(float v) {
#pragma unroll
    for (int o = 16; o > 0; o >>= 1) v += __shfl_xor_sync(0xffffffffu, v, o);
    return v;
}

template <int NK>
__device__ void attn_body2(int n, int U, int lane, int w, int off, int h, int tid,
                           float* __restrict__ Ksh,
                           const float* __restrict__ Qcls,
                           const float* __restrict__ ucnt,
                           float* __restrict__ avgw)
{
    bool a0 = (w < U), a1 = (w + 8 < U);
    float sc0[NK], sc1[NK];
#pragma unroll
    for (int k = 0; k < NK; k++) { sc0[k] = 0.f; sc1[k] = 0.f; }
    const float* Q0 = &Qcls[w * 64];
    const float* Q1 = &Qcls[(w + 8) * 64];

    // pass 0: K columns [0,32)
    if (a1) {
        for (int c = 0; c < 32; c++) {
            float q0 = Q0[c], q1 = Q1[c];
            float kv[NK];
#pragma unroll
            for (int k = 0; k < NK; k++) kv[k] = Ksh[(lane + 32 * k) * KS2 + c];
#pragma unroll
            for (int k = 0; k < NK; k++) { sc0[k] = fmaf(q0, kv[k], sc0[k]); sc1[k] = fmaf(q1, kv[k], sc1[k]); }
        }
    } else if (a0) {
        for (int c = 0; c < 32; c++) {
            float q0 = Q0[c];
#pragma unroll
            for (int k = 0; k < NK; k++) sc0[k] = fmaf(q0, Ksh[(lane + 32 * k) * KS2 + c], sc0[k]);
        }
    }
    __syncthreads();
    for (int idx = tid; idx < n * 32; idx += 256) {
        int s = idx >> 5, c = idx & 31;
        Ksh[s * KS2 + c] = g_K[(size_t)(off + s) * 512 + h * 64 + 32 + c];
    }
    __syncthreads();
    // pass 1: K columns [32,64)
    if (a1) {
        for (int c = 0; c < 32; c++) {
            float q0 = Q0[32 + c], q1 = Q1[32 + c];
            float kv[NK];
#pragma unroll
            for (int k = 0; k < NK; k++) kv[k] = Ksh[(lane + 32 * k) * KS2 + c];
#pragma unroll
            for (int k = 0; k < NK; k++) { sc0[k] = fmaf(q0, kv[k], sc0[k]); sc1[k] = fmaf(q1, kv[k], sc1[k]); }
        }
    } else if (a0) {
        for (int c = 0; c < 32; c++) {
            float q0 = Q0[32 + c];
#pragma unroll
            for (int k = 0; k < NK; k++) sc0[k] = fmaf(q0, Ksh[(lane + 32 * k) * KS2 + c], sc0[k]);
        }
    }

    if (!a0) return;   // no active class; syncs already done

    float aacc[NK];
#pragma unroll
    for (int k = 0; k < NK; k++) aacc[k] = 0.f;

    int ncls = a1 ? 2 : 1;
    for (int uu = 0; uu < ncls; uu++) {
        float* sc = uu ? sc1 : sc0;
        float cnt = ucnt[uu ? (w + 8) : w];
        float m = -1e30f;
#pragma unroll
        for (int k = 0; k < NK; k++) {
            float v = (lane + 32 * k < n) ? sc[k] * 0.125f : -1e30f;
            sc[k] = v;
            m = fmaxf(m, v);
        }
        m = warp_max(m);
        float lsum = 0.f;
#pragma unroll
        for (int k = 0; k < NK; k++) {
            float e = __expf(sc[k] - m);
            sc[k] = e;
            lsum += e;
        }
        float scale = cnt / warp_sum(lsum);
#pragma unroll
        for (int k = 0; k < NK; k++) aacc[k] += sc[k] * scale;
    }
#pragma unroll
    for (int k = 0; k < NK; k++) {
        int s = lane + 32 * k;
        if (s < n) atomicAdd(&avgw[s], aacc[k]);
    }
}

#define ATT_SMEM ((6336 + 1024 + 192 + 192 + 16 + 16 + 12) * 4)

__global__ void __launch_bounds__(256) attn_kernel(const float* __restrict__ bq)
{
    int g = blockIdx.x, h = blockIdx.y;
    int ntrue = g_counts[g];
    int off = g_offsets[g];
    extern __shared__ float sm[];
    float*    Ksh   = sm;
    float*    Qcls  = Ksh + MAX_N * KS2;
    float*    avgw  = Qcls + QMAX * 64;
    unsigned* hpack = (unsigned*)(avgw + MAX_N);
    unsigned* uhp   = hpack + MAX_N;
    float*    ucnt  = (float*)(uhp + QMAX);
    int*      wcnt  = (int*)(ucnt + QMAX);

    int tid = threadIdx.x, lane = tid & 31, w = tid >> 5;

    if (ntrue <= 0) return;
    int n = ntrue < MAX_N ? ntrue : MAX_N;

    for (int idx = tid; idx < n * 32; idx += 256) {
        int s = idx >> 5, c = idx & 31;
        Ksh[s * KS2 + c] = g_K[(size_t)(off + s) * 512 + h * 64 + c];
    }
    for (int idx = tid; idx < MAX_N; idx += 256) avgw[idx] = 0.f;
    if (tid < QMAX) { ucnt[tid] = 0.f; uhp[tid] = 0u; }
    for (int t = tid; t < n; t += 256) {
        unsigned p = 0;
#pragma unroll
        for (int j = 0; j < 8; j++) {
            unsigned hh = (unsigned)(8 * t + j) / (unsigned)ntrue;
            if (hh > 7) hh = 7;
            p |= hh << (3 * j);
        }
        hpack[t] = p;
    }
    __syncthreads();

    int t = tid;
    int isb = (t < n) && (t == 0 || hpack[t] != hpack[t - 1]);
    unsigned bits = __ballot_sync(0xffffffffu, isb);
    if (lane == 31) wcnt[w] = __popc(bits);
    __syncthreads();
    if (tid == 0) {
        int s = 0;
#pragma unroll
        for (int i = 0; i < 8; i++) { int c = wcnt[i]; wcnt[i] = s; s += c; }
        wcnt[8] = s;
    }
    __syncthreads();
    int U = wcnt[8];
    if (t < n) {
        int cid = wcnt[w] + __popc(bits & ((2u << lane) - 1u)) - 1;
        if (cid < QMAX) {
            if (isb) uhp[cid] = hpack[t];
            atomicAdd(&ucnt[cid], 1.0f);
        }
    }
    __syncthreads();

    float bq0 = bq[h * 64 + lane], bq1 = bq[h * 64 + 32 + lane];
#pragma unroll
    for (int uu = 0; uu < 2; uu++) {
        int u = w + uu * 8;
        if (u < U) {
            unsigned hp = uhp[u];
            float q0 = bq0, q1 = bq1;
#pragma unroll
            for (int j = 0; j < 8; j++) {
                int hh = (hp >> (3 * j)) & 7;
                const float* wb = &g_Wqb[h * 4096 + (j * 8 + hh) * 64];
                q0 += wb[lane];
                q1 += wb[lane + 32];
            }
            Qcls[u * 64 + lane] = q0;
            Qcls[u * 64 + 32 + lane] = q1;
        }
    }
    __syncthreads();

    int nk = (n + 31) >> 5;
    switch (nk) {
        case 1: attn_body2<1>(n, U, lane, w, off, h, tid, Ksh, Qcls, ucnt, avgw); break;
        case 2: attn_body2<2>(n, U, lane, w, off, h, tid, Ksh, Qcls, ucnt, avgw); break;
        case 3: attn_body2<3>(n, U, lane, w, off, h, tid, Ksh, Qcls, ucnt, avgw); break;
        case 4: attn_body2<4>(n, U, lane, w, off, h, tid, Ksh, Qcls, ucnt, avgw); break;
        case 5: attn_body2<5>(n, U, lane, w, off, h, tid, Ksh, Qcls, ucnt, avgw); break;
        default: attn_body2<6>(n, U, lane, w, off, h, tid, Ksh, Qcls, ucnt, avgw); break;
    }
    __syncthreads();

    float inv = 1.0f / (float)ntrue;
    for (int s = tid; s < n; s += 256)
        g_avgw[((size_t)g * HEADS + h) * MAX_N + s] = avgw[s] * inv;
}

// ---------------- host launcher ----------------
extern "C" void kernel_launch(void* const* d_in, const int* in_sizes, int n_in,
                              void* d_out, int out_size)
{
    const float* x  = (const float*)d_in[0];
    const int*   bi = (const int*)  d_in[1];
    const float* gq = (const float*)d_in[2];
    const float* wq = (const float*)d_in[3];
    const float* bq = (const float*)d_in[4];
    const float* wk = (const float*)d_in[5];
    const float* bk = (const float*)d_in[6];
    const float* wv = (const float*)d_in[7];
    const float* bv = (const float*)d_in[8];
    const float* wo = (const float*)d_in[9];
    const float* bo = (const float*)d_in[10];
    const float* wp = (const float*)d_in[11];
    const float* bp = (const float*)d_in[12];
    float* out = (float*)d_out;

    void *pPooled, *pTmp;
    cudaGetSymbolAddress(&pPooled, g_pooled);
    cudaGetSymbolAddress(&pTmp, g_tmp);

    cudaFuncSetAttribute(kv_gemm_kernel, cudaFuncAttributeMaxDynamicSharedMemorySize, GEMM_SMEM);

    // launch order: setup+convx(1), kv_gemm(2), attn(3), xbar(4 = profiled slot)
    setup_kernel<<<193 + 16384, 512>>>(gq, wq, bi, bk, wk, x);

    kv_gemm_kernel<<<dim3(512 / BN, N_NODES / BM), 128, GEMM_SMEM>>>();

    attn_kernel<<<dim3(NUM_G, HEADS), 256, ATT_SMEM>>>(bq);

    xbar_kernel<<<dim3(NUM_G, XPARTS), 256>>>(x);
    vproj_kernel<<<dim3(NUM_G / 64, HEADS), 128>>>(wv, bv);

    sgemm32_kernel<false><<<dim3(16, 16), 128>>>(
        (const float*)pPooled, wo, bo, (float*)pTmp, NUM_G, DIM, DIM);
    sgemm32_kernel<true><<<dim3(16, 16), 128>>>(
        (const float*)pTmp, wp, bp, out, NUM_G, DIM, DIM);
}

// round 15
// speedup vs baseline: 1.1517x; 1.0590x over previous
#include <cuda_runtime.h>
#include <cuda_bf16.h>
#include <math.h>
#include <stdint.h>

#define N_NODES   65536
#define NUM_G     512
#define MAX_N     192
#define DIM       512
#define HEADS     8
#define DH        64
#define QMAX      16
#define KS2       33
#define XPARTS    2

#define BM 128
#define BN 128
#define NCHUNK 24
#define GEMM_SMEM (6 * 16384)

// ---------------- device scratch ----------------
__device__ float         g_K[(size_t)N_NODES * 512];
__device__ __nv_bfloat16 g_Xx[(size_t)N_NODES * 1024];
__device__ __nv_bfloat16 g_Wx[(size_t)512 * 1024];
__device__ float         g_bK[512];
__device__ float         g_Wqb[HEADS * 8 * 8 * 64];
__device__ float         g_avgw[NUM_G * HEADS * MAX_N];
__device__ float         g_xbar[XPARTS * NUM_G * HEADS * DIM];
__device__ float         g_pooled[NUM_G * DIM];
__device__ float         g_tmp[NUM_G * DIM];
__device__ int           g_counts[NUM_G];
__device__ int           g_offsets[NUM_G];

// ---------------- helpers ----------------
__device__ __forceinline__ uint32_t smem_u32(const void* p) {
    uint32_t a;
    asm("{ .reg .u64 t; cvta.to.shared.u64 t, %1; cvt.u32.u64 %0, t; }" : "=r"(a) : "l"(p));
    return a;
}
#define SWZ(b) ((b) ^ (((b) >> 3) & 0x70))

__device__ __forceinline__ void cp_async16(uint32_t dst, const void* src) {
    asm volatile("cp.async.cg.shared.global [%0], [%1], 16;" :: "r"(dst), "l"(src));
}
__device__ __forceinline__ void cp_commit() {
    asm volatile("cp.async.commit_group;" ::: "memory");
}
template <int N> __device__ __forceinline__ void cp_wait() {
    asm volatile("cp.async.wait_group %0;" :: "n"(N) : "memory");
}
__device__ __forceinline__ void ldm_x4(uint32_t& r0, uint32_t& r1, uint32_t& r2, uint32_t& r3,
                                       uint32_t addr) {
    asm volatile("ldmatrix.sync.aligned.m8n8.x4.shared.b16 {%0,%1,%2,%3}, [%4];"
                 : "=r"(r0), "=r"(r1), "=r"(r2), "=r"(r3) : "r"(addr));
}
__device__ __forceinline__ void mma_bf16(float& d0, float& d1, float& d2, float& d3,
                                         uint32_t a0, uint32_t a1, uint32_t a2, uint32_t a3,
                                         uint32_t b0, uint32_t b1) {
    asm volatile("mma.sync.aligned.m16n8k16.row.col.f32.bf16.bf16.f32 "
                 "{%0,%1,%2,%3}, {%4,%5,%6,%7}, {%8,%9}, {%0,%1,%2,%3};"
                 : "+f"(d0), "+f"(d1), "+f"(d2), "+f"(d3)
                 : "r"(a0), "r"(a1), "r"(a2), "r"(a3), "r"(b0), "r"(b1));
}

__device__ __forceinline__ void split4(float4 v, uint2* hi, uint2* lo) {
    __nv_bfloat16 h0 = __float2bfloat16_rn(v.x), h1 = __float2bfloat16_rn(v.y);
    __nv_bfloat16 h2 = __float2bfloat16_rn(v.z), h3 = __float2bfloat16_rn(v.w);
    __nv_bfloat16 l0 = __float2bfloat16_rn(v.x - __bfloat162float(h0));
    __nv_bfloat16 l1 = __float2bfloat16_rn(v.y - __bfloat162float(h1));
    __nv_bfloat16 l2 = __float2bfloat16_rn(v.z - __bfloat162float(h2));
    __nv_bfloat16 l3 = __float2bfloat16_rn(v.w - __bfloat162float(h3));
    hi->x = (uint32_t)__bfloat16_as_ushort(h0) | ((uint32_t)__bfloat16_as_ushort(h1) << 16);
    hi->y = (uint32_t)__bfloat16_as_ushort(h2) | ((uint32_t)__bfloat16_as_ushort(h3) << 16);
    lo->x = (uint32_t)__bfloat16_as_ushort(l0) | ((uint32_t)__bfloat16_as_ushort(l1) << 16);
    lo->y = (uint32_t)__bfloat16_as_ushort(l2) | ((uint32_t)__bfloat16_as_ushort(l3) << 16);
}

// ---------------- setup: wqb(0-63) + counts(64) + convw(65-192) ----------------
__global__ void __launch_bounds__(512) setup_kernel(
    const float* __restrict__ gq, const float* __restrict__ wq,
    const int* __restrict__ bidx, const float* __restrict__ bk,
    const float* __restrict__ wk)
{
    __shared__ float sbuf[512 + 64 * 65];
    int b = blockIdx.x;
    int tid = threadIdx.x;

    if (b < 64) {
        int h = b >> 3, j = b & 7;
        float* gqs = sbuf;
        float* wsh = sbuf + 512;
        gqs[tid] = gq[tid];
        for (int idx = tid; idx < 64 * 64; idx += 512) {
            int row = idx >> 6, cc = idx & 63;
            wsh[row * 65 + cc] = wq[(size_t)(h * 64 + row) * 512 + j * 64 + cc];
        }
        __syncthreads();
        int ol = tid & 63, hh = tid >> 6;
        float v = 0.f;
#pragma unroll 8
        for (int r = 0; r < 64; r++) v += gqs[hh * 64 + r] * wsh[ol * 65 + r];
        g_Wqb[h * 4096 + (j * 8 + hh) * 64 + ol] = v;
    } else if (b == 64) {
        int* lb = (int*)sbuf;
        int g = tid;
        int lo = 0, hi = N_NODES;
        while (lo < hi) { int mid = (lo + hi) >> 1; if (bidx[mid] < g) lo = mid + 1; else hi = mid; }
        lb[g] = lo;
        if (g == 0) lb[NUM_G] = N_NODES;
        __syncthreads();
        g_offsets[g] = lb[g];
        g_counts[g]  = lb[g + 1] - lb[g];
        g_bK[g] = bk[g];
    } else {
        int i = (b - 65) * 512 + tid;
        int r = i >> 7;
        int c4 = i & 127;
        float4 v = ((const float4*)wk)[(size_t)r * 128 + c4];
        uint2 hi, lo;
        split4(v, &hi, &lo);
        ((uint2*)(g_Wx + (size_t)r * 1024))[c4]       = hi;
        ((uint2*)(g_Wx + (size_t)r * 1024 + 512))[c4] = lo;
    }
}

// ---------------- convx ----------------
__global__ void __launch_bounds__(256) convx_kernel(const float* __restrict__ x) {
    size_t i = (size_t)blockIdx.x * 256 + threadIdx.x;
    float4 v = ((const float4*)x)[i];
    size_t r = i >> 7;
    int c4 = (int)(i & 127);
    uint2 hi, lo;
    split4(v, &hi, &lo);
    ((uint2*)(g_Xx + r * 1024))[c4]       = hi;
    ((uint2*)(g_Xx + r * 1024 + 512))[c4] = lo;
}

// ---------------- bf16 mma.sync K GEMM: 4 warps of 64x64 ----------------
__device__ __forceinline__ int a_index(int c) { return (c < 16) ? (c >> 1) : (c - 8); }

__device__ __forceinline__ void gemm_load_chunk(uint32_t sbase, int m0, int n0, int c, int tid) {
    int kq, kx, kw;
    bool loadA;
    if (c < 16) { kq = c >> 1; kx = kq * 64;       kw = kq * 64 + ((c & 1) ? 512 : 0); loadA = !(c & 1); }
    else        { kq = c - 16; kx = kq * 64 + 512; kw = kq * 64;                        loadA = true; }
    uint32_t sA = sbase + (uint32_t)(a_index(c) % 3) * 16384u;
    uint32_t sB = sbase + 49152u + (uint32_t)(c % 3) * 16384u;
    if (loadA) {
#pragma unroll
        for (int u = 0; u < 8; u++) {
            int idx = tid + u * 128;
            int row = idx >> 3;
            int cb = (idx & 7) * 16;
            cp_async16(sA + SWZ(row * 128 + cb),
                       (const char*)(g_Xx + (size_t)(m0 + row) * 1024 + kx) + cb);
        }
    }
#pragma unroll
    for (int u = 0; u < 8; u++) {
        int idx = tid + u * 128;
        int row = idx >> 3;
        int cb = (idx & 7) * 16;
        cp_async16(sB + SWZ(row * 128 + cb),
                   (const char*)(g_Wx + (size_t)(n0 + row) * 1024 + kw) + cb);
    }
    cp_commit();
}

__global__ void __launch_bounds__(128, 2) kv_gemm_kernel() {
    extern __shared__ char smem[];
    uint32_t sbase = smem_u32(smem);
    int tid = threadIdx.x;
    int lane = tid & 31, w = tid >> 5;
    int wm = w >> 1, wn = w & 1;
    int m0 = blockIdx.y * BM;
    int n0 = blockIdx.x * BN;

    float acc[4][8][4];
#pragma unroll
    for (int i = 0; i < 4; i++)
#pragma unroll
        for (int j = 0; j < 8; j++)
#pragma unroll
            for (int k = 0; k < 4; k++) acc[i][j][k] = 0.f;

    gemm_load_chunk(sbase, m0, n0, 0, tid);
    gemm_load_chunk(sbase, m0, n0, 1, tid);

    int lrow = ((lane >> 3) & 1) * 8 + (lane & 7);
    int lcol = ((lane >> 4) & 1) * 16;

    for (int c = 0; c < NCHUNK; c++) {
        if (c < NCHUNK - 1) cp_wait<1>(); else cp_wait<0>();
        __syncthreads();
        if (c + 2 < NCHUNK) gemm_load_chunk(sbase, m0, n0, c + 2, tid);

        uint32_t sA = sbase + (uint32_t)(a_index(c) % 3) * 16384u;
        uint32_t sB = sbase + 49152u + (uint32_t)(c % 3) * 16384u;

#pragma unroll
        for (int ks = 0; ks < 4; ks++) {
            uint32_t a[4][4], b[4][4];
#pragma unroll
            for (int mt = 0; mt < 4; mt++) {
                uint32_t addr = sA + SWZ((wm * 64 + mt * 16 + lrow) * 128 + ks * 32 + lcol);
                ldm_x4(a[mt][0], a[mt][1], a[mt][2], a[mt][3], addr);
            }
#pragma unroll
            for (int nt = 0; nt < 4; nt++) {
                uint32_t addr = sB + SWZ((wn * 64 + nt * 16 + lrow) * 128 + ks * 32 + lcol);
                ldm_x4(b[nt][0], b[nt][1], b[nt][2], b[nt][3], addr);
            }
#pragma unroll
            for (int mt = 0; mt < 4; mt++)
#pragma unroll
                for (int nt = 0; nt < 8; nt++) {
                    uint32_t b0 = b[nt >> 1][(nt & 1) ? 1 : 0];
                    uint32_t b1 = b[nt >> 1][(nt & 1) ? 3 : 2];
                    mma_bf16(acc[mt][nt][0], acc[mt][nt][1], acc[mt][nt][2], acc[mt][nt][3],
                             a[mt][0], a[mt][1], a[mt][2], a[mt][3], b0, b1);
                }
        }
    }

    int mrow = lane >> 2;
    int ncol = (lane & 3) * 2;
#pragma unroll
    for (int mt = 0; mt < 4; mt++) {
#pragma unroll
        for (int nt = 0; nt < 8; nt++) {
            int m = m0 + wm * 64 + mt * 16 + mrow;
            int n = n0 + wn * 64 + nt * 8 + ncol;
            float2 bias = *(const float2*)&g_bK[n];
            float2 v0 = make_float2(acc[mt][nt][0] + bias.x, acc[mt][nt][1] + bias.y);
            float2 v1 = make_float2(acc[mt][nt][2] + bias.x, acc[mt][nt][3] + bias.y);
            *(float2*)&g_K[(size_t)m * 512 + n] = v0;
            *(float2*)&g_K[(size_t)(m + 8) * 512 + n] = v1;
        }
    }
}

// ---------------- small SGEMM 32x32 tiles ----------------
template <bool RELU>
__global__ void __launch_bounds__(128) sgemm32_kernel(
    const float* __restrict__ A, const float* __restrict__ B,
    const float* __restrict__ bias, float* __restrict__ C,
    int M, int N, int K)
{
    __shared__ float As[16][32];
    __shared__ float Bs[16][32];
    int tid = threadIdx.x;
    int m0 = blockIdx.y * 32;
    int n0 = blockIdx.x * 32;
    int tr = tid >> 3, tc = tid & 7;
    int lr = tid >> 2;
    int lc = (tid & 3) * 4;
    float acc[2][4];
#pragma unroll
    for (int i = 0; i < 2; i++)
#pragma unroll
        for (int j = 0; j < 4; j++) acc[i][j] = 0.f;

    for (int k0 = 0; k0 < K; k0 += 16) {
        float4 a = *(const float4*)(A + (size_t)(m0 + lr) * K + k0 + lc);
        As[lc + 0][lr] = a.x; As[lc + 1][lr] = a.y; As[lc + 2][lr] = a.z; As[lc + 3][lr] = a.w;
        float4 b = *(const float4*)(B + (size_t)(n0 + lr) * K + k0 + lc);
        Bs[lc + 0][lr] = b.x; Bs[lc + 1][lr] = b.y; Bs[lc + 2][lr] = b.z; Bs[lc + 3][lr] = b.w;
        __syncthreads();
#pragma unroll
        for (int kk = 0; kk < 16; kk++) {
            float am[2], bn[4];
#pragma unroll
            for (int i = 0; i < 2; i++) am[i] = As[kk][tr * 2 + i];
#pragma unroll
            for (int j = 0; j < 4; j++) bn[j] = Bs[kk][tc * 4 + j];
#pragma unroll
            for (int i = 0; i < 2; i++)
#pragma unroll
                for (int j = 0; j < 4; j++) acc[i][j] = fmaf(am[i], bn[j], acc[i][j]);
        }
        __syncthreads();
    }
#pragma unroll
    for (int i = 0; i < 2; i++) {
        int m = m0 + tr * 2 + i;
#pragma unroll
        for (int j = 0; j < 4; j++) {
            int n = n0 + tc * 4 + j;
            float v = acc[i][j] + bias[n];
            if (RELU) v = fmaxf(v, 0.f);
            C[(size_t)m * N + n] = v;
        }
    }
}

// ---------------- V projection on xbar (sums XPARTS partials) ----------------
__global__ void __launch_bounds__(128) vproj_kernel(const float* __restrict__ wv,
                                                    const float* __restrict__ bv)
{
    __shared__ float As[16][64];
    __shared__ float Bs[16][64];
    int tid = threadIdx.x;
    int h = blockIdx.y;
    int m0 = blockIdx.x * 64;
    int tr = tid >> 3, tc = tid & 7;
    int lr = tid >> 2;
    int lc = (tid & 3) * 4;
    float acc[4][8];
#pragma unroll
    for (int i = 0; i < 4; i++)
#pragma unroll
        for (int j = 0; j < 8; j++) acc[i][j] = 0.f;

    const size_t PSTRIDE = (size_t)NUM_G * HEADS * DIM;

    for (int k0 = 0; k0 < 512; k0 += 16) {
#pragma unroll
        for (int p = 0; p < 2; p++) {
            int r = lr + 32 * p;
            size_t base = ((size_t)(m0 + r) * 8 + h) * 512 + k0 + lc;
            float4 a = *(const float4*)(g_xbar + base);
#pragma unroll
            for (int q = 1; q < XPARTS; q++) {
                float4 a2 = *(const float4*)(g_xbar + q * PSTRIDE + base);
                a.x += a2.x; a.y += a2.y; a.z += a2.z; a.w += a2.w;
            }
            As[lc + 0][r] = a.x; As[lc + 1][r] = a.y; As[lc + 2][r] = a.z; As[lc + 3][r] = a.w;
            float4 b = *(const float4*)(wv + (size_t)(h * 64 + r) * 512 + k0 + lc);
            Bs[lc + 0][r] = b.x; Bs[lc + 1][r] = b.y; Bs[lc + 2][r] = b.z; Bs[lc + 3][r] = b.w;
        }
        __syncthreads();
#pragma unroll
        for (int kk = 0; kk < 16; kk++) {
            float am[4], bn[8];
#pragma unroll
            for (int i = 0; i < 4; i++) am[i] = As[kk][tr * 4 + i];
#pragma unroll
            for (int j = 0; j < 8; j++) bn[j] = Bs[kk][tc * 8 + j];
#pragma unroll
            for (int i = 0; i < 4; i++)
#pragma unroll
                for (int j = 0; j < 8; j++) acc[i][j] = fmaf(am[i], bn[j], acc[i][j]);
        }
        __syncthreads();
    }
#pragma unroll
    for (int i = 0; i < 4; i++) {
        int m = m0 + tr * 4 + i;
        int cnt = g_counts[m];
        int nn = cnt < MAX_N ? cnt : MAX_N;
        float scale = (cnt > 0) ? (float)nn / (float)cnt : 0.f;
#pragma unroll
        for (int j = 0; j < 8; j++) {
            int nc = tc * 8 + j;
            g_pooled[(size_t)m * DIM + h * 64 + nc] = acc[i][j] + scale * bv[h * 64 + nc];
        }
    }
}

// ---------------- xbar: s-split partials, unrolled with prefetch ----------------
__global__ void __launch_bounds__(256) xbar_kernel(const float* __restrict__ x) {
    int g = blockIdx.x;
    int part = blockIdx.y;
    int ntrue = g_counts[g];
    int off = g_offsets[g];
    int n = ntrue < MAX_N ? ntrue : MAX_N;
    __shared__ float aw[HEADS * MAX_N];
    int tid = threadIdx.x;

    float acc[HEADS][2];
#pragma unroll
    for (int h = 0; h < HEADS; h++) { acc[h][0] = 0.f; acc[h][1] = 0.f; }

    if (n > 0) {
#pragma unroll
        for (int h = 0; h < HEADS; h++)
            for (int s = tid; s < n; s += 256)
                aw[h * MAX_N + s] = g_avgw[((size_t)g * HEADS + h) * MAX_N + s];
        __syncthreads();

        const float* xb = x + (size_t)off * 512;
        int s = part;
        for (; s + XPARTS < n; s += 2 * XPARTS) {
            int s2 = s + XPARTS;
            float x0a = xb[(size_t)s  * 512 + tid];
            float x1a = xb[(size_t)s  * 512 + tid + 256];
            float x0b = xb[(size_t)s2 * 512 + tid];
            float x1b = xb[(size_t)s2 * 512 + tid + 256];
#pragma unroll
            for (int h = 0; h < HEADS; h++) {
                float wa = aw[h * MAX_N + s];
                float wb = aw[h * MAX_N + s2];
                acc[h][0] = fmaf(wa, x0a, acc[h][0]);
                acc[h][1] = fmaf(wa, x1a, acc[h][1]);
                acc[h][0] = fmaf(wb, x0b, acc[h][0]);
                acc[h][1] = fmaf(wb, x1b, acc[h][1]);
            }
        }
        if (s < n) {
            float x0 = xb[(size_t)s * 512 + tid];
            float x1 = xb[(size_t)s * 512 + tid + 256];
#pragma unroll
            for (int h = 0; h < HEADS; h++) {
                float wv = aw[h * MAX_N + s];
                acc[h][0] = fmaf(wv, x0, acc[h][0]);
                acc[h][1] = fmaf(wv, x1, acc[h][1]);
            }
        }
    }
    size_t pbase = (size_t)part * NUM_G * HEADS * DIM;
#pragma unroll
    for (int h = 0; h < HEADS; h++) {
        g_xbar[pbase + ((size_t)g * HEADS + h) * 512 + tid]       = acc[h][0];
        g_xbar[pbase + ((size_t)g * HEADS + h) * 512 + tid + 256] = acc[h][1];
    }
}

// ---------------- attention: Q-class + two-pass K + dead-class skip ----------------
__device__ __forceinline__ float warp_max(float v) {
#pragma unroll
    for (int o = 16; o > 0; o >>= 1) v = fmaxf(v, __shfl_xor_sync(0xffffffffu, v, o));
    return v;
}
__device__ __forceinline__ float warp_sum(float v) {
#pragma unroll
    for (int o = 16; o > 0; o >>= 1) v += __shfl_xor_sync(0xffffffffu, v, o);
    return v;
}

template <int NK>
__device__ void attn_body2(int n, int U, int lane, int w, int off, int h, int tid,
                           float* __restrict__ Ksh,
                           const float* __restrict__ Qcls,
                           const float* __restrict__ ucnt,
                           float* __restrict__ avgw)
{
    bool a0 = (w < U), a1 = (w + 8 < U);
    float sc0[NK], sc1[NK];
#pragma unroll
    for (int k = 0; k < NK; k++) { sc0[k] = 0.f; sc1[k] = 0.f; }
    const float* Q0 = &Qcls[w * 64];
    const float* Q1 = &Qcls[(w + 8) * 64];

    if (a1) {
        for (int c = 0; c < 32; c++) {
            float q0 = Q0[c], q1 = Q1[c];
            float kv[NK];
#pragma unroll
            for (int k = 0; k < NK; k++) kv[k] = Ksh[(lane + 32 * k) * KS2 + c];
#pragma unroll
            for (int k = 0; k < NK; k++) { sc0[k] = fmaf(q0, kv[k], sc0[k]); sc1[k] = fmaf(q1, kv[k], sc1[k]); }
        }
    } else if (a0) {
        for (int c = 0; c < 32; c++) {
            float q0 = Q0[c];
#pragma unroll
            for (int k = 0; k < NK; k++) sc0[k] = fmaf(q0, Ksh[(lane + 32 * k) * KS2 + c], sc0[k]);
        }
    }
    __syncthreads();
    for (int idx = tid; idx < n * 32; idx += 256) {
        int s = idx >> 5, c = idx & 31;
        Ksh[s * KS2 + c] = g_K[(size_t)(off + s) * 512 + h * 64 + 32 + c];
    }
    __syncthreads();
    if (a1) {
        for (int c = 0; c < 32; c++) {
            float q0 = Q0[32 + c], q1 = Q1[32 + c];
            float kv[NK];
#pragma unroll
            for (int k = 0; k < NK; k++) kv[k] = Ksh[(lane + 32 * k) * KS2 + c];
#pragma unroll
            for (int k = 0; k < NK; k++) { sc0[k] = fmaf(q0, kv[k], sc0[k]); sc1[k] = fmaf(q1, kv[k], sc1[k]); }
        }
    } else if (a0) {
        for (int c = 0; c < 32; c++) {
            float q0 = Q0[32 + c];
#pragma unroll
            for (int k = 0; k < NK; k++) sc0[k] = fmaf(q0, Ksh[(lane + 32 * k) * KS2 + c], sc0[k]);
        }
    }

    if (!a0) return;

    float aacc[NK];
#pragma unroll
    for (int k = 0; k < NK; k++) aacc[k] = 0.f;

    int ncls = a1 ? 2 : 1;
    for (int uu = 0; uu < ncls; uu++) {
        float* sc = uu ? sc1 : sc0;
        float cnt = ucnt[uu ? (w + 8) : w];
        float m = -1e30f;
#pragma unroll
        for (int k = 0; k < NK; k++) {
            float v = (lane + 32 * k < n) ? sc[k] * 0.125f : -1e30f;
            sc[k] = v;
            m = fmaxf(m, v);
        }
        m = warp_max(m);
        float lsum = 0.f;
#pragma unroll
        for (int k = 0; k < NK; k++) {
            float e = __expf(sc[k] - m);
            sc[k] = e;
            lsum += e;
        }
        float scale = cnt / warp_sum(lsum);
#pragma unroll
        for (int k = 0; k < NK; k++) aacc[k] += sc[k] * scale;
    }
#pragma unroll
    for (int k = 0; k < NK; k++) {
        int s = lane + 32 * k;
        if (s < n) atomicAdd(&avgw[s], aacc[k]);
    }
}

#define ATT_SMEM ((6336 + 1024 + 192 + 192 + 16 + 16 + 12) * 4)

__global__ void __launch_bounds__(256) attn_kernel(const float* __restrict__ bq)
{
    int g = blockIdx.x, h = blockIdx.y;
    int ntrue = g_counts[g];
    int off = g_offsets[g];
    extern __shared__ float sm[];
    float*    Ksh   = sm;
    float*    Qcls  = Ksh + MAX_N * KS2;
    float*    avgw  = Qcls + QMAX * 64;
    unsigned* hpack = (unsigned*)(avgw + MAX_N);
    unsigned* uhp   = hpack + MAX_N;
    float*    ucnt  = (float*)(uhp + QMAX);
    int*      wcnt  = (int*)(ucnt + QMAX);

    int tid = threadIdx.x, lane = tid & 31, w = tid >> 5;

    if (ntrue <= 0) return;
    int n = ntrue < MAX_N ? ntrue : MAX_N;

    for (int idx = tid; idx < n * 32; idx += 256) {
        int s = idx >> 5, c = idx & 31;
        Ksh[s * KS2 + c] = g_K[(size_t)(off + s) * 512 + h * 64 + c];
    }
    for (int idx = tid; idx < MAX_N; idx += 256) avgw[idx] = 0.f;
    if (tid < QMAX) { ucnt[tid] = 0.f; uhp[tid] = 0u; }
    for (int t = tid; t < n; t += 256) {
        unsigned p = 0;
#pragma unroll
        for (int j = 0; j < 8; j++) {
            unsigned hh = (unsigned)(8 * t + j) / (unsigned)ntrue;
            if (hh > 7) hh = 7;
            p |= hh << (3 * j);
        }
        hpack[t] = p;
    }
    __syncthreads();

    int t = tid;
    int isb = (t < n) && (t == 0 || hpack[t] != hpack[t - 1]);
    unsigned bits = __ballot_sync(0xffffffffu, isb);
    if (lane == 31) wcnt[w] = __popc(bits);
    __syncthreads();
    if (tid == 0) {
        int s = 0;
#pragma unroll
        for (int i = 0; i < 8; i++) { int c = wcnt[i]; wcnt[i] = s; s += c; }
        wcnt[8] = s;
    }
    __syncthreads();
    int U = wcnt[8];
    if (t < n) {
        int cid = wcnt[w] + __popc(bits & ((2u << lane) - 1u)) - 1;
        if (cid < QMAX) {
            if (isb) uhp[cid] = hpack[t];
            atomicAdd(&ucnt[cid], 1.0f);
        }
    }
    __syncthreads();

    float bq0 = bq[h * 64 + lane], bq1 = bq[h * 64 + 32 + lane];
#pragma unroll
    for (int uu = 0; uu < 2; uu++) {
        int u = w + uu * 8;
        if (u < U) {
            unsigned hp = uhp[u];
            float q0 = bq0, q1 = bq1;
#pragma unroll
            for (int j = 0; j < 8; j++) {
                int hh = (hp >> (3 * j)) & 7;
                const float* wb = &g_Wqb[h * 4096 + (j * 8 + hh) * 64];
                q0 += wb[lane];
                q1 += wb[lane + 32];
            }
            Qcls[u * 64 + lane] = q0;
            Qcls[u * 64 + 32 + lane] = q1;
        }
    }
    __syncthreads();

    int nk = (n + 31) >> 5;
    switch (nk) {
        case 1: attn_body2<1>(n, U, lane, w, off, h, tid, Ksh, Qcls, ucnt, avgw); break;
        case 2: attn_body2<2>(n, U, lane, w, off, h, tid, Ksh, Qcls, ucnt, avgw); break;
        case 3: attn_body2<3>(n, U, lane, w, off, h, tid, Ksh, Qcls, ucnt, avgw); break;
        case 4: attn_body2<4>(n, U, lane, w, off, h, tid, Ksh, Qcls, ucnt, avgw); break;
        case 5: attn_body2<5>(n, U, lane, w, off, h, tid, Ksh, Qcls, ucnt, avgw); break;
        default: attn_body2<6>(n, U, lane, w, off, h, tid, Ksh, Qcls, ucnt, avgw); break;
    }
    __syncthreads();

    float inv = 1.0f / (float)ntrue;
    for (int s = tid; s < n; s += 256)
        g_avgw[((size_t)g * HEADS + h) * MAX_N + s] = avgw[s] * inv;
}

// ---------------- host launcher ----------------
extern "C" void kernel_launch(void* const* d_in, const int* in_sizes, int n_in,
                              void* d_out, int out_size)
{
    const float* x  = (const float*)d_in[0];
    const int*   bi = (const int*)  d_in[1];
    const float* gq = (const float*)d_in[2];
    const float* wq = (const float*)d_in[3];
    const float* bq = (const float*)d_in[4];
    const float* wk = (const float*)d_in[5];
    const float* bk = (const float*)d_in[6];
    const float* wv = (const float*)d_in[7];
    const float* bv = (const float*)d_in[8];
    const float* wo = (const float*)d_in[9];
    const float* bo = (const float*)d_in[10];
    const float* wp = (const float*)d_in[11];
    const float* bp = (const float*)d_in[12];
    float* out = (float*)d_out;

    void *pPooled, *pTmp;
    cudaGetSymbolAddress(&pPooled, g_pooled);
    cudaGetSymbolAddress(&pTmp, g_tmp);

    cudaFuncSetAttribute(kv_gemm_kernel, cudaFuncAttributeMaxDynamicSharedMemorySize, GEMM_SMEM);

    // launch order: setup(1), convx(2), kv_gemm(3), attn(4 = profiled slot)
    setup_kernel<<<193, 512>>>(gq, wq, bi, bk, wk);
    convx_kernel<<<32768, 256>>>(x);

    kv_gemm_kernel<<<dim3(512 / BN, N_NODES / BM), 128, GEMM_SMEM>>>();

    attn_kernel<<<dim3(NUM_G, HEADS), 256, ATT_SMEM>>>(bq);

    xbar_kernel<<<dim3(NUM_G, XPARTS), 256>>>(x);
    vproj_kernel<<<dim3(NUM_G / 64, HEADS), 128>>>(wv, bv);

    sgemm32_kernel<false><<<dim3(16, 16), 128>>>(
        (const float*)pPooled, wo, bo, (float*)pTmp, NUM_G, DIM, DIM);
    sgemm32_kernel<true><<<dim3(16, 16), 128>>>(
        (const float*)pTmp, wp, bp, out, NUM_G, DIM, DIM);
}